// round 2
// baseline (speedup 1.0000x reference)
#include <cuda_runtime.h>
#include <math.h>

// ---------------- problem constants ----------------
#define BB 128      // batch
#define NN 49       // spatial tokens
#define CIN 2048
#define GG 256      // query groups
#define DD 768      // model dim
#define HH 8        // heads
#define HD 96       // head dim
#define FF 2048
#define NCLS 12547
#define DUP 50

// ---------------- scratch (device globals; no allocations allowed) ----------
__device__ float g_mem [BB * NN * DD];   // relu(x@We+be)
__device__ float g_k   [BB * NN * DD];
__device__ float g_v   [BB * NN * DD];
__device__ float g_t1  [GG * DD];        // LN(2*query)  (batch independent)
__device__ float g_q   [GG * DD];        // (t1@Wq+bq)/sqrt(96)
__device__ float g_attno[BB * GG * DD];  // attn out; later reused as ffn2 out
__device__ float g_oproj[BB * GG * DD];  // o@Wo+bo; later reused as h
__device__ float g_t2  [BB * GG * DD];
__device__ float g_ff  [BB * GG * FF];

// ---------------- generic fp32 SGEMM: C = act(alpha*(A@B + bias)) -----------
// A: [M,K] row-major, B: [K,N] row-major, bias: [N].
// Requires M%128==0, N%128==0, K%8==0 (all shapes here satisfy this).
#define BM 128
#define BN 128
#define BKK 8
#define TM 8
#define TN 8

template <int RELU>
__global__ __launch_bounds__(256)
void sgemm_kernel(const float* __restrict__ A, const float* __restrict__ B,
                  const float* __restrict__ bias, float* __restrict__ C,
                  int M, int N, int K, float alpha)
{
    __shared__ float As[BKK][BM];
    __shared__ float Bs[BKK][BN];

    const int tid = threadIdx.x;
    const int bx = blockIdx.x, by = blockIdx.y;

    const float* Ab = A + (size_t)by * BM * K;
    const float* Bb = B + (size_t)bx * BN;
    float*       Cb = C + (size_t)by * BM * N + (size_t)bx * BN;

    const int arow = tid >> 1;          // 0..127
    const int acol = (tid & 1) * 4;     // 0 or 4
    const int brow = tid >> 5;          // 0..7
    const int bcol = (tid & 31) * 4;    // 0..124

    const int tx = (tid % 16) * TN;     // output col offset in tile
    const int ty = (tid / 16) * TM;     // output row offset in tile

    float acc[TM][TN] = {};

    for (int k0 = 0; k0 < K; k0 += BKK) {
        float4 a4 = *reinterpret_cast<const float4*>(Ab + (size_t)arow * K + k0 + acol);
        As[acol + 0][arow] = a4.x;
        As[acol + 1][arow] = a4.y;
        As[acol + 2][arow] = a4.z;
        As[acol + 3][arow] = a4.w;
        *reinterpret_cast<float4*>(&Bs[brow][bcol]) =
            *reinterpret_cast<const float4*>(Bb + (size_t)(k0 + brow) * N + bcol);
        __syncthreads();

        #pragma unroll
        for (int kk = 0; kk < BKK; kk++) {
            float4 a0 = *reinterpret_cast<const float4*>(&As[kk][ty]);
            float4 a1 = *reinterpret_cast<const float4*>(&As[kk][ty + 4]);
            float4 b0 = *reinterpret_cast<const float4*>(&Bs[kk][tx]);
            float4 b1 = *reinterpret_cast<const float4*>(&Bs[kk][tx + 4]);
            float ra[TM] = {a0.x, a0.y, a0.z, a0.w, a1.x, a1.y, a1.z, a1.w};
            float rb[TN] = {b0.x, b0.y, b0.z, b0.w, b1.x, b1.y, b1.z, b1.w};
            #pragma unroll
            for (int i = 0; i < TM; i++)
                #pragma unroll
                for (int j = 0; j < TN; j++)
                    acc[i][j] += ra[i] * rb[j];
        }
        __syncthreads();
    }

    #pragma unroll
    for (int i = 0; i < TM; i++) {
        float4 o0, o1;
        float* oo0 = &o0.x; float* oo1 = &o1.x;
        #pragma unroll
        for (int j = 0; j < 4; j++) {
            float v0 = alpha * (acc[i][j]     + bias[bx * BN + tx + j]);
            float v1 = alpha * (acc[i][j + 4] + bias[bx * BN + tx + 4 + j]);
            if (RELU) { v0 = fmaxf(v0, 0.f); v1 = fmaxf(v1, 0.f); }
            oo0[j] = v0; oo1[j] = v1;
        }
        *reinterpret_cast<float4*>(Cb + (size_t)(ty + i) * N + tx)     = o0;
        *reinterpret_cast<float4*>(Cb + (size_t)(ty + i) * N + tx + 4) = o1;
    }
}

// ---------------- LayerNorm over D=768 ---------------------------------------
// mode 0: x = 2*a[row]           (t1 = LN(2*query))
// mode 1: x = a[row] + r[row%G]  (t2 = LN(t1 + oproj))
// mode 2: x = a[row] + r[row]    (h  = LN(t2 + ffn))
__global__ __launch_bounds__(256)
void ln_kernel(const float* __restrict__ a, const float* __restrict__ r,
               const float* __restrict__ gamma, const float* __restrict__ beta,
               float* __restrict__ out, int mode)
{
    const int row = blockIdx.x;
    const int t = threadIdx.x;
    const float* ap = a + (size_t)row * DD;

    float x[3];
    #pragma unroll
    for (int j = 0; j < 3; j++) {
        const int idx = t + j * 256;
        float val = ap[idx];
        if (mode == 0)      val = 2.f * val;
        else if (mode == 1) val += r[(size_t)(row & (GG - 1)) * DD + idx];
        else                val += r[(size_t)row * DD + idx];
        x[j] = val;
    }
    float s1 = x[0] + x[1] + x[2];
    float s2 = x[0] * x[0] + x[1] * x[1] + x[2] * x[2];
    #pragma unroll
    for (int off = 16; off; off >>= 1) {
        s1 += __shfl_xor_sync(0xffffffffu, s1, off);
        s2 += __shfl_xor_sync(0xffffffffu, s2, off);
    }
    __shared__ float sh1[8], sh2[8];
    const int w = t >> 5, lane = t & 31;
    if (lane == 0) { sh1[w] = s1; sh2[w] = s2; }
    __syncthreads();
    float S1 = 0.f, S2 = 0.f;
    #pragma unroll
    for (int i = 0; i < 8; i++) { S1 += sh1[i]; S2 += sh2[i]; }
    const float mean = S1 * (1.f / (float)DD);
    const float var  = S2 * (1.f / (float)DD) - mean * mean;
    const float rstd = rsqrtf(var + 1e-5f);

    float* op = out + (size_t)row * DD;
    #pragma unroll
    for (int j = 0; j < 3; j++) {
        const int idx = t + j * 256;
        op[idx] = (x[j] - mean) * rstd * gamma[idx] + beta[idx];
    }
}

// ---------------- fused cross-attention (softmax over N=49) ------------------
// q: [G,D] pre-scaled by 1/sqrt(96) (bias included); k,v: [B,N,D]; o: [B,G,D]
// grid (H, B), 256 threads = one query per thread.
__global__ __launch_bounds__(256)
void attn_kernel(const float* __restrict__ q, const float* __restrict__ k,
                 const float* __restrict__ v, float* __restrict__ o)
{
    __shared__ float ks[NN][HD];
    __shared__ float vs[NN][HD];
    const int h = blockIdx.x, b = blockIdx.y;
    const int t = threadIdx.x;

    for (int i = t; i < NN * HD; i += 256) {
        const int n = i / HD, d = i % HD;
        const size_t gi = ((size_t)(b * NN + n)) * DD + h * HD + d;
        ks[n][d] = k[gi];
        vs[n][d] = v[gi];
    }
    __syncthreads();

    const int g = t;
    float4 qv[HD / 4];
    const float4* qp = reinterpret_cast<const float4*>(q + (size_t)g * DD + h * HD);
    #pragma unroll
    for (int i = 0; i < HD / 4; i++) qv[i] = qp[i];

    float s[NN];
    #pragma unroll 7
    for (int n = 0; n < NN; n++) {
        const float4* kp = reinterpret_cast<const float4*>(ks[n]);
        float acc = 0.f;
        #pragma unroll
        for (int i = 0; i < HD / 4; i++) {
            float4 kk = kp[i];
            acc += qv[i].x * kk.x + qv[i].y * kk.y + qv[i].z * kk.z + qv[i].w * kk.w;
        }
        s[n] = acc;
    }
    float m = -1e30f;
    #pragma unroll
    for (int n = 0; n < NN; n++) m = fmaxf(m, s[n]);
    float sum = 0.f;
    #pragma unroll
    for (int n = 0; n < NN; n++) { s[n] = __expf(s[n] - m); sum += s[n]; }
    const float inv = 1.f / sum;

    float* op = o + ((size_t)(b * GG + g)) * DD + h * HD;
    #pragma unroll
    for (int d4 = 0; d4 < HD / 4; d4++) {
        float4 acc = {0.f, 0.f, 0.f, 0.f};
        #pragma unroll 7
        for (int n = 0; n < NN; n++) {
            const float p = s[n];
            float4 vv = *reinterpret_cast<const float4*>(&vs[n][d4 * 4]);
            acc.x += p * vv.x; acc.y += p * vv.y; acc.z += p * vv.z; acc.w += p * vv.w;
        }
        acc.x *= inv; acc.y *= inv; acc.z *= inv; acc.w *= inv;
        *reinterpret_cast<float4*>(op + d4 * 4) = acc;
    }
}

// ---------------- GroupFC: logits[b, g*50+f] = h[b,g,:]·Wg[g,:,f] + bg -------
// grid (B/64, G), 256 threads, 64(b) x 64(f-padded) tile, K-chunks of 32.
__global__ __launch_bounds__(256)
void groupfc_kernel(const float* __restrict__ h, const float* __restrict__ Wg,
                    const float* __restrict__ bg, float* __restrict__ out)
{
    const int g  = blockIdx.y;
    const int b0 = blockIdx.x * 64;
    __shared__ float hs[32][65];  // [d][b]
    __shared__ float ws[32][65];  // [d][f]
    const int t = threadIdx.x;
    const int tx = (t % 16) * 4;  // f
    const int ty = (t / 16) * 4;  // b
    float acc[4][4] = {};

    for (int d0 = 0; d0 < DD; d0 += 32) {
        for (int i = t; i < 64 * 32; i += 256) {
            const int bi = i / 32, di = i % 32;
            hs[di][bi] = h[((size_t)(b0 + bi) * GG + g) * DD + d0 + di];
        }
        for (int i = t; i < 32 * 64; i += 256) {
            const int di = i / 64, fi = i % 64;
            ws[di][fi] = (fi < DUP) ? Wg[((size_t)g * DD + d0 + di) * DUP + fi] : 0.f;
        }
        __syncthreads();
        #pragma unroll
        for (int d = 0; d < 32; d++) {
            float rh[4], rb[4];
            #pragma unroll
            for (int i = 0; i < 4; i++) rh[i] = hs[d][ty + i];
            #pragma unroll
            for (int j = 0; j < 4; j++) rb[j] = ws[d][tx + j];
            #pragma unroll
            for (int i = 0; i < 4; i++)
                #pragma unroll
                for (int j = 0; j < 4; j++)
                    acc[i][j] += rh[i] * rb[j];
        }
        __syncthreads();
    }
    #pragma unroll
    for (int i = 0; i < 4; i++) {
        #pragma unroll
        for (int j = 0; j < 4; j++) {
            const int f = tx + j;
            if (f < DUP) {
                const int c = g * DUP + f;
                if (c < NCLS)
                    out[(size_t)(b0 + ty + i) * NCLS + c] = acc[i][j] + bg[c];
            }
        }
    }
}

// ---------------- launch -----------------------------------------------------
static float* sym(const void* s) { void* p = nullptr; cudaGetSymbolAddress(&p, s); return (float*)p; }

extern "C" void kernel_launch(void* const* d_in, const int* in_sizes, int n_in,
                              void* d_out, int out_size)
{
    (void)in_sizes; (void)n_in; (void)out_size;
    const float* x      = (const float*)d_in[0];
    const float* We     = (const float*)d_in[1];
    const float* be     = (const float*)d_in[2];
    const float* query  = (const float*)d_in[3];
    const float* Wq     = (const float*)d_in[4];
    const float* bq     = (const float*)d_in[5];
    const float* Wk     = (const float*)d_in[6];
    const float* bk     = (const float*)d_in[7];
    const float* Wv     = (const float*)d_in[8];
    const float* bv     = (const float*)d_in[9];
    const float* Wo     = (const float*)d_in[10];
    const float* bo     = (const float*)d_in[11];
    const float* g1     = (const float*)d_in[12];
    const float* beta1  = (const float*)d_in[13];
    const float* g2     = (const float*)d_in[14];
    const float* beta2  = (const float*)d_in[15];
    const float* g3     = (const float*)d_in[16];
    const float* beta3  = (const float*)d_in[17];
    const float* W1     = (const float*)d_in[18];
    const float* b1     = (const float*)d_in[19];
    const float* W2     = (const float*)d_in[20];
    const float* b2     = (const float*)d_in[21];
    const float* Wg     = (const float*)d_in[22];
    const float* bg     = (const float*)d_in[23];
    float* out = (float*)d_out;

    float *p_mem = sym(g_mem), *p_k = sym(g_k), *p_v = sym(g_v);
    float *p_t1 = sym(g_t1), *p_q = sym(g_q);
    float *p_attno = sym(g_attno), *p_oproj = sym(g_oproj);
    float *p_t2 = sym(g_t2), *p_ff = sym(g_ff);

    const float qscale = 0.10206207261596577f;  // 1/sqrt(96)

    // t1 = LN(2*query); q = (t1@Wq + bq) * qscale   (batch independent)
    ln_kernel<<<GG, 256>>>(query, nullptr, g1, beta1, p_t1, 0);
    sgemm_kernel<0><<<dim3(DD / BN, GG / BM), 256>>>(p_t1, Wq, bq, p_q, GG, DD, DD, qscale);

    // mem = relu(x @ We + be)
    sgemm_kernel<1><<<dim3(DD / BN, (BB * NN) / BM), 256>>>(x, We, be, p_mem, BB * NN, DD, CIN, 1.f);
    // k,v projections
    sgemm_kernel<0><<<dim3(DD / BN, (BB * NN) / BM), 256>>>(p_mem, Wk, bk, p_k, BB * NN, DD, DD, 1.f);
    sgemm_kernel<0><<<dim3(DD / BN, (BB * NN) / BM), 256>>>(p_mem, Wv, bv, p_v, BB * NN, DD, DD, 1.f);

    // fused attention
    attn_kernel<<<dim3(HH, BB), 256>>>(p_q, p_k, p_v, p_attno);

    // output projection + residual LN
    sgemm_kernel<0><<<dim3(DD / BN, (BB * GG) / BM), 256>>>(p_attno, Wo, bo, p_oproj, BB * GG, DD, DD, 1.f);
    ln_kernel<<<BB * GG, 256>>>(p_oproj, p_t1, g2, beta2, p_t2, 1);

    // FFN (g_attno reused for ffn2 output, g_oproj reused for h)
    sgemm_kernel<1><<<dim3(FF / BN, (BB * GG) / BM), 256>>>(p_t2, W1, b1, p_ff, BB * GG, FF, DD, 1.f);
    sgemm_kernel<0><<<dim3(DD / BN, (BB * GG) / BM), 256>>>(p_ff, W2, b2, p_attno, BB * GG, DD, FF, 1.f);
    ln_kernel<<<BB * GG, 256>>>(p_attno, p_t2, g3, beta3, p_oproj, 2);

    // GroupFC
    groupfc_kernel<<<dim3(BB / 64, GG), 256>>>(p_oproj, Wg, bg, out);
}

// round 6
// speedup vs baseline: 2.2280x; 2.2280x over previous
#include <cuda_runtime.h>
#include <cuda_bf16.h>
#include <math.h>
#include <stdint.h>

// ---------------- problem constants ----------------
#define BB 128      // batch
#define NN 49       // spatial tokens
#define CIN 2048
#define GG 256      // query groups
#define DD 768      // model dim
#define HH 8        // heads
#define HD 96       // head dim
#define FF 2048
#define NCLS 12547
#define DUP 50

// ---------------- asm helpers (sm_80+ features only) -------------------------
__device__ __forceinline__ uint32_t smem_u32(const void* p) {
    uint32_t a;
    asm("{ .reg .u64 t; cvta.to.shared.u64 t, %1; cvt.u32.u64 %0, t; }" : "=r"(a) : "l"(p));
    return a;
}
#define CP16(dst, src) \
    asm volatile("cp.async.cg.shared.global [%0], [%1], 16;" :: "r"(dst), "l"(src))
#define CP_COMMIT() asm volatile("cp.async.commit_group;" ::: "memory")
#define CP_WAIT(n)  asm volatile("cp.async.wait_group %0;" :: "n"(n) : "memory")
#define LDSM4(r, addr) \
    asm volatile("ldmatrix.sync.aligned.m8n8.x4.shared.b16 {%0,%1,%2,%3}, [%4];" \
                 : "=r"((r)[0]), "=r"((r)[1]), "=r"((r)[2]), "=r"((r)[3]) : "r"(addr))
#define MMA_BF16(c, a, b0, b1) \
    asm volatile("mma.sync.aligned.m16n8k16.row.col.f32.bf16.bf16.f32 " \
                 "{%0,%1,%2,%3},{%4,%5,%6,%7},{%8,%9},{%0,%1,%2,%3};" \
                 : "+f"((c)[0]), "+f"((c)[1]), "+f"((c)[2]), "+f"((c)[3]) \
                 : "r"((a)[0]), "r"((a)[1]), "r"((a)[2]), "r"((a)[3]), "r"(b0), "r"(b1))

__device__ __forceinline__ void split2(float v, __nv_bfloat16& h, __nv_bfloat16& l) {
    h = __float2bfloat16(v);
    l = __float2bfloat16(v - __bfloat162float(h));
}

// ---------------- scratch (device globals) -----------------------------------
// fp32
__device__ float g_k    [BB * NN * DD];
__device__ float g_v    [BB * NN * DD];
__device__ float g_t1   [GG * DD];
__device__ float g_q    [GG * DD];
__device__ float g_oproj[BB * GG * DD];   // Wo out; later reused as h
__device__ float g_t2   [BB * GG * DD];
__device__ float g_ffn2 [BB * GG * DD];
// bf16 hi/lo activation operands
__device__ __nv_bfloat16 g_xh [BB * NN * CIN], g_xl [BB * NN * CIN];
__device__ __nv_bfloat16 g_mh [BB * NN * DD],  g_ml [BB * NN * DD];
__device__ __nv_bfloat16 g_t1h[GG * DD],       g_t1l[GG * DD];
__device__ __nv_bfloat16 g_aoh[BB * GG * DD],  g_aol[BB * GG * DD];
__device__ __nv_bfloat16 g_t2h[BB * GG * DD],  g_t2l[BB * GG * DD];
__device__ __nv_bfloat16 g_ffh[BB * GG * FF],  g_ffl[BB * GG * FF];
// transposed+split weights: [N,K] bf16
__device__ __nv_bfloat16 tWe_hi[DD * CIN], tWe_lo[DD * CIN];
__device__ __nv_bfloat16 tWq_hi[DD * DD],  tWq_lo[DD * DD];
__device__ __nv_bfloat16 tWk_hi[DD * DD],  tWk_lo[DD * DD];
__device__ __nv_bfloat16 tWv_hi[DD * DD],  tWv_lo[DD * DD];
__device__ __nv_bfloat16 tWo_hi[DD * DD],  tWo_lo[DD * DD];
__device__ __nv_bfloat16 tW1_hi[FF * DD],  tW1_lo[FF * DD];
__device__ __nv_bfloat16 tW2_hi[DD * FF],  tW2_lo[DD * FF];

// ---------------- weight transpose + hi/lo split: W[K,N] -> hi/lo [N,K] ------
__global__ __launch_bounds__(256)
void split_transpose(const float* __restrict__ W, __nv_bfloat16* __restrict__ hi,
                     __nv_bfloat16* __restrict__ lo, int K, int N)
{
    __shared__ float tile[32][33];
    const int tx = threadIdx.x & 31, ty = threadIdx.x >> 5;
    const int kb = blockIdx.y * 32, nb = blockIdx.x * 32;
    #pragma unroll
    for (int i = 0; i < 4; i++)
        tile[ty + i * 8][tx] = W[(size_t)(kb + ty + i * 8) * N + nb + tx];
    __syncthreads();
    #pragma unroll
    for (int i = 0; i < 4; i++) {
        const int n = nb + ty + i * 8, k = kb + tx;
        __nv_bfloat16 h, l;
        split2(tile[tx][ty + i * 8], h, l);
        hi[(size_t)n * K + k] = h;
        lo[(size_t)n * K + k] = l;
    }
}

// ---------------- elementwise fp32 -> bf16 hi/lo (for x) ---------------------
__global__ __launch_bounds__(256)
void convert_split(const float* __restrict__ in, __nv_bfloat16* __restrict__ hi,
                   __nv_bfloat16* __restrict__ lo)
{
    const int i = (blockIdx.x * 256 + threadIdx.x) * 4;
    float4 v = *reinterpret_cast<const float4*>(in + i);
    __nv_bfloat16 h0, l0, h1, l1, h2, l2, h3, l3;
    split2(v.x, h0, l0); split2(v.y, h1, l1);
    split2(v.z, h2, l2); split2(v.w, h3, l3);
    __nv_bfloat162 ha(h0, h1), hb(h2, h3), la(l0, l1), lb(l2, l3);
    *reinterpret_cast<__nv_bfloat162*>(hi + i)     = ha;
    *reinterpret_cast<__nv_bfloat162*>(hi + i + 2) = hb;
    *reinterpret_cast<__nv_bfloat162*>(lo + i)     = la;
    *reinterpret_cast<__nv_bfloat162*>(lo + i + 2) = lb;
}

// ---------------- bf16 hi/lo tensor-core GEMM --------------------------------
// C = act(alpha*(A @ B^T + bias));  A hi/lo [M,K], B hi/lo [N,K] bf16.
// 3-pass: Ah*Bh + Ah*Bl + Al*Bh.  BM=BN=128, BK=32, 8 warps x (64x32).
// M%128==0, N%128==0, K%32==0.
#define LDSH 40                      // smem row stride in halves (80B, conflict-free)
#define TILE_H (128 * LDSH)          // 5120 halves = 10240B per tile
#define STAGE_B (4 * TILE_H * 2)     // 40960B per stage (Ah,Al,Bh,Bl)
#define GEMM_SMEM (2 * STAGE_B)      // 81920B

template <int RELU, int SPLIT>
__global__ __launch_bounds__(256, 2)
void tc_gemm(const __nv_bfloat16* __restrict__ Ah, const __nv_bfloat16* __restrict__ Al,
             const __nv_bfloat16* __restrict__ Bh, const __nv_bfloat16* __restrict__ Bl,
             const float* __restrict__ bias, float* __restrict__ Cf,
             __nv_bfloat16* __restrict__ Ch, __nv_bfloat16* __restrict__ Cl,
             int M, int N, int K, float alpha)
{
    extern __shared__ __nv_bfloat16 sm[];
    const uint32_t sb = smem_u32(sm);
    const int tid = threadIdx.x, wid = tid >> 5, lane = tid & 31;
    const int wm = wid & 1, wn = wid >> 1;             // warp tile: rows wm*64, cols wn*32
    const int m0 = blockIdx.y * 128, n0 = blockIdx.x * 128;
    const int nst = K >> 5;

    const __nv_bfloat16* srcs[4] = {Ah, Al, Bh, Bl};

    // ---- async stage loader: 8 x 16B per thread ----
    auto load_stage = [&](int s, int buf) {
        const int k0 = s << 5;
        const uint32_t d0 = sb + buf * STAGE_B;
        #pragma unroll
        for (int i = 0; i < 8; i++) {
            const int tile = i >> 1;                     // 0:Ah 1:Al 2:Bh 3:Bl
            const int c = (i & 1) * 256 + tid;           // 0..511
            const int row = c >> 2, part = c & 3;
            const int base_row = (tile < 2) ? m0 : n0;
            const __nv_bfloat16* src = srcs[tile] +
                (size_t)(base_row + row) * K + k0 + part * 8;
            const uint32_t dst = d0 + tile * (TILE_H * 2) + row * (LDSH * 2) + part * 16;
            CP16(dst, src);
        }
        CP_COMMIT();
    };

    float acc[4][4][4];
    #pragma unroll
    for (int i = 0; i < 4; i++)
        #pragma unroll
        for (int j = 0; j < 4; j++)
            #pragma unroll
            for (int q = 0; q < 4; q++) acc[i][j][q] = 0.f;

    load_stage(0, 0);

    // ldmatrix lane addressing (halves)
    const int a_r = (lane & 15), a_c8 = (lane >> 4) * 8;
    const int b_r = ((lane >> 4) & 1) * 8 + (lane & 7);
    const int b_c8 = ((lane >> 3) & 1) * 8;

    #pragma unroll 1
    for (int s = 0; s < nst; s++) {
        const int buf = s & 1;
        if (s + 1 < nst) load_stage(s + 1, buf ^ 1);
        if (s + 1 < nst) { CP_WAIT(1); } else { CP_WAIT(0); }
        __syncthreads();

        const uint32_t ab = sb + buf * STAGE_B;
        const uint32_t alb = ab + TILE_H * 2;
        const uint32_t bb = ab + 2 * TILE_H * 2;
        const uint32_t blb = ab + 3 * TILE_H * 2;

        #pragma unroll
        for (int ks = 0; ks < 2; ks++) {
            const int kh = ks * 16;
            uint32_t fAh[4][4], fAl[4][4], fBh[2][4], fBl[2][4];
            #pragma unroll
            for (int i = 0; i < 4; i++) {
                const uint32_t off = ((wm * 64 + i * 16 + a_r) * LDSH + kh + a_c8) * 2;
                LDSM4(fAh[i], ab + off);
                LDSM4(fAl[i], alb + off);
            }
            #pragma unroll
            for (int j = 0; j < 2; j++) {
                const uint32_t off = ((wn * 32 + j * 16 + b_r) * LDSH + kh + b_c8) * 2;
                LDSM4(fBh[j], bb + off);
                LDSM4(fBl[j], blb + off);
            }
            #pragma unroll
            for (int n = 0; n < 4; n++) {
                const int j = n >> 1, h = (n & 1) * 2;
                const uint32_t bh0 = fBh[j][h], bh1 = fBh[j][h + 1];
                const uint32_t bl0 = fBl[j][h], bl1 = fBl[j][h + 1];
                #pragma unroll
                for (int i = 0; i < 4; i++) {
                    MMA_BF16(acc[i][n], fAh[i], bh0, bh1);
                    MMA_BF16(acc[i][n], fAh[i], bl0, bl1);
                    MMA_BF16(acc[i][n], fAl[i], bh0, bh1);
                }
            }
        }
        __syncthreads();
    }

    // ---- epilogue ----
    const int row0 = m0 + wm * 64 + (lane >> 2);
    const int col0 = n0 + wn * 32 + (lane & 3) * 2;
    #pragma unroll
    for (int i = 0; i < 4; i++) {
        #pragma unroll
        for (int j = 0; j < 4; j++) {
            const int r = row0 + i * 16;
            const int c = col0 + j * 8;
            const float b0 = bias[c], b1 = bias[c + 1];
            float v0 = alpha * (acc[i][j][0] + b0);
            float v1 = alpha * (acc[i][j][1] + b1);
            float v2 = alpha * (acc[i][j][2] + b0);
            float v3 = alpha * (acc[i][j][3] + b1);
            if (RELU) {
                v0 = fmaxf(v0, 0.f); v1 = fmaxf(v1, 0.f);
                v2 = fmaxf(v2, 0.f); v3 = fmaxf(v3, 0.f);
            }
            if (!SPLIT) {
                *reinterpret_cast<float2*>(Cf + (size_t)r * N + c)       = make_float2(v0, v1);
                *reinterpret_cast<float2*>(Cf + (size_t)(r + 8) * N + c) = make_float2(v2, v3);
            } else {
                __nv_bfloat16 h0, l0, h1, l1, h2, l2, h3, l3;
                split2(v0, h0, l0); split2(v1, h1, l1);
                split2(v2, h2, l2); split2(v3, h3, l3);
                *reinterpret_cast<__nv_bfloat162*>(Ch + (size_t)r * N + c)       = __nv_bfloat162(h0, h1);
                *reinterpret_cast<__nv_bfloat162*>(Cl + (size_t)r * N + c)       = __nv_bfloat162(l0, l1);
                *reinterpret_cast<__nv_bfloat162*>(Ch + (size_t)(r + 8) * N + c) = __nv_bfloat162(h2, h3);
                *reinterpret_cast<__nv_bfloat162*>(Cl + (size_t)(r + 8) * N + c) = __nv_bfloat162(l2, l3);
            }
        }
    }
}

// ---------------- LayerNorm over D=768 (optional bf16 hi/lo side output) -----
__global__ __launch_bounds__(256)
void ln_kernel(const float* __restrict__ a, const float* __restrict__ r,
               const float* __restrict__ gamma, const float* __restrict__ beta,
               float* __restrict__ out, __nv_bfloat16* __restrict__ oh,
               __nv_bfloat16* __restrict__ ol, int mode)
{
    const int row = blockIdx.x;
    const int t = threadIdx.x;
    const float* ap = a + (size_t)row * DD;

    float x[3];
    #pragma unroll
    for (int j = 0; j < 3; j++) {
        const int idx = t + j * 256;
        float val = ap[idx];
        if (mode == 0)      val = 2.f * val;
        else if (mode == 1) val += r[(size_t)(row & (GG - 1)) * DD + idx];
        else                val += r[(size_t)row * DD + idx];
        x[j] = val;
    }
    float s1 = x[0] + x[1] + x[2];
    float s2 = x[0] * x[0] + x[1] * x[1] + x[2] * x[2];
    #pragma unroll
    for (int off = 16; off; off >>= 1) {
        s1 += __shfl_xor_sync(0xffffffffu, s1, off);
        s2 += __shfl_xor_sync(0xffffffffu, s2, off);
    }
    __shared__ float sh1[8], sh2[8];
    const int w = t >> 5, lane = t & 31;
    if (lane == 0) { sh1[w] = s1; sh2[w] = s2; }
    __syncthreads();
    float S1 = 0.f, S2 = 0.f;
    #pragma unroll
    for (int i = 0; i < 8; i++) { S1 += sh1[i]; S2 += sh2[i]; }
    const float mean = S1 * (1.f / (float)DD);
    const float var  = S2 * (1.f / (float)DD) - mean * mean;
    const float rstd = rsqrtf(var + 1e-5f);

    #pragma unroll
    for (int j = 0; j < 3; j++) {
        const int idx = t + j * 256;
        const float v = (x[j] - mean) * rstd * gamma[idx] + beta[idx];
        out[(size_t)row * DD + idx] = v;
        if (oh) {
            __nv_bfloat16 h, l;
            split2(v, h, l);
            oh[(size_t)row * DD + idx] = h;
            ol[(size_t)row * DD + idx] = l;
        }
    }
}

// ---------------- fused cross-attention, bf16 hi/lo output -------------------
__global__ __launch_bounds__(256)
void attn_kernel(const float* __restrict__ q, const float* __restrict__ k,
                 const float* __restrict__ v, __nv_bfloat16* __restrict__ oh,
                 __nv_bfloat16* __restrict__ ol)
{
    __shared__ float ks[NN][HD];
    __shared__ float vs[NN][HD];
    const int h = blockIdx.x, b = blockIdx.y;
    const int t = threadIdx.x;

    for (int i = t; i < NN * HD; i += 256) {
        const int n = i / HD, d = i % HD;
        const size_t gi = ((size_t)(b * NN + n)) * DD + h * HD + d;
        ks[n][d] = k[gi];
        vs[n][d] = v[gi];
    }
    __syncthreads();

    const int g = t;
    float4 qv[HD / 4];
    const float4* qp = reinterpret_cast<const float4*>(q + (size_t)g * DD + h * HD);
    #pragma unroll
    for (int i = 0; i < HD / 4; i++) qv[i] = qp[i];

    float s[NN];
    #pragma unroll 7
    for (int n = 0; n < NN; n++) {
        const float4* kp = reinterpret_cast<const float4*>(ks[n]);
        float acc = 0.f;
        #pragma unroll
        for (int i = 0; i < HD / 4; i++) {
            float4 kk = kp[i];
            acc += qv[i].x * kk.x + qv[i].y * kk.y + qv[i].z * kk.z + qv[i].w * kk.w;
        }
        s[n] = acc;
    }
    float m = -1e30f;
    #pragma unroll
    for (int n = 0; n < NN; n++) m = fmaxf(m, s[n]);
    float sum = 0.f;
    #pragma unroll
    for (int n = 0; n < NN; n++) { s[n] = __expf(s[n] - m); sum += s[n]; }
    const float inv = 1.f / sum;

    const size_t ob = ((size_t)(b * GG + g)) * DD + h * HD;
    #pragma unroll
    for (int d4 = 0; d4 < HD / 4; d4++) {
        float4 acc = {0.f, 0.f, 0.f, 0.f};
        #pragma unroll 7
        for (int n = 0; n < NN; n++) {
            const float p = s[n];
            float4 vv = *reinterpret_cast<const float4*>(&vs[n][d4 * 4]);
            acc.x += p * vv.x; acc.y += p * vv.y; acc.z += p * vv.z; acc.w += p * vv.w;
        }
        acc.x *= inv; acc.y *= inv; acc.z *= inv; acc.w *= inv;
        __nv_bfloat16 h0, l0, h1, l1, h2, l2, h3, l3;
        split2(acc.x, h0, l0); split2(acc.y, h1, l1);
        split2(acc.z, h2, l2); split2(acc.w, h3, l3);
        *reinterpret_cast<__nv_bfloat162*>(oh + ob + d4 * 4)     = __nv_bfloat162(h0, h1);
        *reinterpret_cast<__nv_bfloat162*>(oh + ob + d4 * 4 + 2) = __nv_bfloat162(h2, h3);
        *reinterpret_cast<__nv_bfloat162*>(ol + ob + d4 * 4)     = __nv_bfloat162(l0, l1);
        *reinterpret_cast<__nv_bfloat162*>(ol + ob + d4 * 4 + 2) = __nv_bfloat162(l2, l3);
    }
}

// ---------------- GroupFC ----------------------------------------------------
__global__ __launch_bounds__(256)
void groupfc_kernel(const float* __restrict__ h, const float* __restrict__ Wg,
                    const float* __restrict__ bg, float* __restrict__ out)
{
    const int g  = blockIdx.y;
    const int b0 = blockIdx.x * 64;
    __shared__ float hs[32][65];
    __shared__ float ws[32][65];
    const int t = threadIdx.x;
    const int tx = (t % 16) * 4;
    const int ty = (t / 16) * 4;
    float acc[4][4] = {};

    for (int d0 = 0; d0 < DD; d0 += 32) {
        for (int i = t; i < 64 * 32; i += 256) {
            const int bi = i / 32, di = i % 32;
            hs[di][bi] = h[((size_t)(b0 + bi) * GG + g) * DD + d0 + di];
        }
        for (int i = t; i < 32 * 64; i += 256) {
            const int di = i / 64, fi = i % 64;
            ws[di][fi] = (fi < DUP) ? Wg[((size_t)g * DD + d0 + di) * DUP + fi] : 0.f;
        }
        __syncthreads();
        #pragma unroll
        for (int d = 0; d < 32; d++) {
            float rh[4], rb[4];
            #pragma unroll
            for (int i = 0; i < 4; i++) rh[i] = hs[d][ty + i];
            #pragma unroll
            for (int j = 0; j < 4; j++) rb[j] = ws[d][tx + j];
            #pragma unroll
            for (int i = 0; i < 4; i++)
                #pragma unroll
                for (int j = 0; j < 4; j++)
                    acc[i][j] += rh[i] * rb[j];
        }
        __syncthreads();
    }
    #pragma unroll
    for (int i = 0; i < 4; i++) {
        #pragma unroll
        for (int j = 0; j < 4; j++) {
            const int f = tx + j;
            if (f < DUP) {
                const int c = g * DUP + f;
                if (c < NCLS)
                    out[(size_t)(b0 + ty + i) * NCLS + c] = acc[i][j] + bg[c];
            }
        }
    }
}

// ---------------- launch -----------------------------------------------------
static float* sym(const void* s) { void* p = nullptr; cudaGetSymbolAddress(&p, s); return (float*)p; }
static __nv_bfloat16* symb(const void* s) { void* p = nullptr; cudaGetSymbolAddress(&p, s); return (__nv_bfloat16*)p; }

extern "C" void kernel_launch(void* const* d_in, const int* in_sizes, int n_in,
                              void* d_out, int out_size)
{
    (void)in_sizes; (void)n_in; (void)out_size;
    const float* x      = (const float*)d_in[0];
    const float* We     = (const float*)d_in[1];
    const float* be     = (const float*)d_in[2];
    const float* query  = (const float*)d_in[3];
    const float* Wq     = (const float*)d_in[4];
    const float* bq     = (const float*)d_in[5];
    const float* Wk     = (const float*)d_in[6];
    const float* bk     = (const float*)d_in[7];
    const float* Wv     = (const float*)d_in[8];
    const float* bv     = (const float*)d_in[9];
    const float* Wo     = (const float*)d_in[10];
    const float* bo     = (const float*)d_in[11];
    const float* g1     = (const float*)d_in[12];
    const float* beta1  = (const float*)d_in[13];
    const float* g2     = (const float*)d_in[14];
    const float* beta2  = (const float*)d_in[15];
    const float* g3     = (const float*)d_in[16];
    const float* beta3  = (const float*)d_in[17];
    const float* W1     = (const float*)d_in[18];
    const float* b1     = (const float*)d_in[19];
    const float* W2     = (const float*)d_in[20];
    const float* b2     = (const float*)d_in[21];
    const float* Wg     = (const float*)d_in[22];
    const float* bg     = (const float*)d_in[23];
    float* out = (float*)d_out;

    float *p_k = sym(g_k), *p_v = sym(g_v), *p_t1 = sym(g_t1), *p_q = sym(g_q);
    float *p_oproj = sym(g_oproj), *p_t2 = sym(g_t2), *p_ffn2 = sym(g_ffn2);
    __nv_bfloat16 *p_xh = symb(g_xh),  *p_xl = symb(g_xl);
    __nv_bfloat16 *p_mh = symb(g_mh),  *p_ml = symb(g_ml);
    __nv_bfloat16 *p_t1h = symb(g_t1h), *p_t1l = symb(g_t1l);
    __nv_bfloat16 *p_aoh = symb(g_aoh), *p_aol = symb(g_aol);
    __nv_bfloat16 *p_t2h = symb(g_t2h), *p_t2l = symb(g_t2l);
    __nv_bfloat16 *p_ffh = symb(g_ffh), *p_ffl = symb(g_ffl);
    __nv_bfloat16 *pWe_h = symb(tWe_hi), *pWe_l = symb(tWe_lo);
    __nv_bfloat16 *pWq_h = symb(tWq_hi), *pWq_l = symb(tWq_lo);
    __nv_bfloat16 *pWk_h = symb(tWk_hi), *pWk_l = symb(tWk_lo);
    __nv_bfloat16 *pWv_h = symb(tWv_hi), *pWv_l = symb(tWv_lo);
    __nv_bfloat16 *pWo_h = symb(tWo_hi), *pWo_l = symb(tWo_lo);
    __nv_bfloat16 *pW1_h = symb(tW1_hi), *pW1_l = symb(tW1_lo);
    __nv_bfloat16 *pW2_h = symb(tW2_hi), *pW2_l = symb(tW2_lo);

    cudaFuncSetAttribute(tc_gemm<0, 0>, cudaFuncAttributeMaxDynamicSharedMemorySize, GEMM_SMEM);
    cudaFuncSetAttribute(tc_gemm<1, 1>, cudaFuncAttributeMaxDynamicSharedMemorySize, GEMM_SMEM);

    const float qscale = 0.10206207261596577f;  // 1/sqrt(96)

    // weight transpose + bf16 hi/lo split
    split_transpose<<<dim3(DD / 32, CIN / 32), 256>>>(We, pWe_h, pWe_l, CIN, DD);
    split_transpose<<<dim3(DD / 32, DD / 32), 256>>>(Wq, pWq_h, pWq_l, DD, DD);
    split_transpose<<<dim3(DD / 32, DD / 32), 256>>>(Wk, pWk_h, pWk_l, DD, DD);
    split_transpose<<<dim3(DD / 32, DD / 32), 256>>>(Wv, pWv_h, pWv_l, DD, DD);
    split_transpose<<<dim3(DD / 32, DD / 32), 256>>>(Wo, pWo_h, pWo_l, DD, DD);
    split_transpose<<<dim3(FF / 32, DD / 32), 256>>>(W1, pW1_h, pW1_l, DD, FF);
    split_transpose<<<dim3(DD / 32, FF / 32), 256>>>(W2, pW2_h, pW2_l, FF, DD);
    // x -> bf16 hi/lo
    convert_split<<<(BB * NN * CIN) / 1024, 256>>>(x, p_xh, p_xl);

    // t1 = LN(2*query) (+split); q = (t1@Wq + bq)/sqrt(96)
    ln_kernel<<<GG, 256>>>(query, nullptr, g1, beta1, p_t1, p_t1h, p_t1l, 0);
    tc_gemm<0, 0><<<dim3(DD / 128, GG / 128), 256, GEMM_SMEM>>>(
        p_t1h, p_t1l, pWq_h, pWq_l, bq, p_q, nullptr, nullptr, GG, DD, DD, qscale);

    // mem = relu(x @ We + be)  -> bf16 hi/lo directly
    tc_gemm<1, 1><<<dim3(DD / 128, (BB * NN) / 128), 256, GEMM_SMEM>>>(
        p_xh, p_xl, pWe_h, pWe_l, be, nullptr, p_mh, p_ml, BB * NN, DD, CIN, 1.f);
    // k, v projections (fp32 out for attention)
    tc_gemm<0, 0><<<dim3(DD / 128, (BB * NN) / 128), 256, GEMM_SMEM>>>(
        p_mh, p_ml, pWk_h, pWk_l, bk, p_k, nullptr, nullptr, BB * NN, DD, DD, 1.f);
    tc_gemm<0, 0><<<dim3(DD / 128, (BB * NN) / 128), 256, GEMM_SMEM>>>(
        p_mh, p_ml, pWv_h, pWv_l, bv, p_v, nullptr, nullptr, BB * NN, DD, DD, 1.f);

    // fused attention -> bf16 hi/lo
    attn_kernel<<<dim3(HH, BB), 256>>>(p_q, p_k, p_v, p_aoh, p_aol);

    // output projection + residual LN (t2 fp32 + split)
    tc_gemm<0, 0><<<dim3(DD / 128, (BB * GG) / 128), 256, GEMM_SMEM>>>(
        p_aoh, p_aol, pWo_h, pWo_l, bo, p_oproj, nullptr, nullptr, BB * GG, DD, DD, 1.f);
    ln_kernel<<<BB * GG, 256>>>(p_oproj, p_t1, g2, beta2, p_t2, p_t2h, p_t2l, 1);

    // FFN: ff = relu(t2@W1+b1) -> bf16 hi/lo; ffn2 = ff@W2+b2 -> fp32
    tc_gemm<1, 1><<<dim3(FF / 128, (BB * GG) / 128), 256, GEMM_SMEM>>>(
        p_t2h, p_t2l, pW1_h, pW1_l, b1, nullptr, p_ffh, p_ffl, BB * GG, FF, DD, 1.f);
    tc_gemm<0, 0><<<dim3(DD / 128, (BB * GG) / 128), 256, GEMM_SMEM>>>(
        p_ffh, p_ffl, pW2_h, pW2_l, b2, p_ffn2, nullptr, nullptr, BB * GG, DD, FF, 1.f);
    ln_kernel<<<BB * GG, 256>>>(p_ffn2, p_t2, g3, beta3, p_oproj, nullptr, nullptr, 2);

    // GroupFC
    groupfc_kernel<<<dim3(BB / 64, GG), 256>>>(p_oproj, Wg, bg, out);
}

// round 7
// speedup vs baseline: 3.0782x; 1.3816x over previous
#include <cuda_runtime.h>
#include <cuda_fp16.h>
#include <math.h>
#include <stdint.h>

// ---------------- problem constants ----------------
#define BB 128      // batch
#define NN 49       // spatial tokens
#define CIN 2048
#define GG 256      // query groups
#define DD 768      // model dim
#define HH 8        // heads
#define HD 96       // head dim
#define FF 2048
#define NCLS 12547
#define DUP 50

// ---------------- asm helpers (sm_80+ features only) -------------------------
__device__ __forceinline__ uint32_t smem_u32(const void* p) {
    uint32_t a;
    asm("{ .reg .u64 t; cvta.to.shared.u64 t, %1; cvt.u32.u64 %0, t; }" : "=r"(a) : "l"(p));
    return a;
}
#define CP16(dst, src) \
    asm volatile("cp.async.cg.shared.global [%0], [%1], 16;" :: "r"(dst), "l"(src))
#define CP_COMMIT() asm volatile("cp.async.commit_group;" ::: "memory")
#define CP_WAIT(n)  asm volatile("cp.async.wait_group %0;" :: "n"(n) : "memory")
#define LDSM4(r, addr) \
    asm volatile("ldmatrix.sync.aligned.m8n8.x4.shared.b16 {%0,%1,%2,%3}, [%4];" \
                 : "=r"((r)[0]), "=r"((r)[1]), "=r"((r)[2]), "=r"((r)[3]) : "r"(addr))
#define MMA_F16(c, a, b0, b1) \
    asm volatile("mma.sync.aligned.m16n8k16.row.col.f32.f16.f16.f32 " \
                 "{%0,%1,%2,%3},{%4,%5,%6,%7},{%8,%9},{%0,%1,%2,%3};" \
                 : "+f"((c)[0]), "+f"((c)[1]), "+f"((c)[2]), "+f"((c)[3]) \
                 : "r"((a)[0]), "r"((a)[1]), "r"((a)[2]), "r"((a)[3]), "r"(b0), "r"(b1))

__device__ __forceinline__ void split2h(float v, __half& h, __half& l) {
    h = __float2half(v);
    l = __float2half(v - __half2float(h));
}

// ---------------- scratch (device globals) -----------------------------------
// fp32
__device__ float g_k    [BB * NN * DD];
__device__ float g_v    [BB * NN * DD];
__device__ float g_t1   [GG * DD];
__device__ float g_q    [GG * DD];
__device__ float g_oproj[BB * GG * DD];   // Wo out; later reused as h
__device__ float g_t2   [BB * GG * DD];
__device__ float g_ffn2 [BB * GG * DD];
// fp16 single-precision activation operands
__device__ __half g_xh [BB * NN * CIN];
__device__ __half g_mh [BB * NN * DD];
__device__ __half g_t1h[GG * DD];
__device__ __half g_aoh[BB * GG * DD];
__device__ __half g_t2h[BB * GG * DD];
__device__ __half g_ffh[BB * GG * FF];
// transposed+split weights: [N,K] fp16 hi/lo
__device__ __half tWe_hi[DD * CIN], tWe_lo[DD * CIN];
__device__ __half tWq_hi[DD * DD],  tWq_lo[DD * DD];
__device__ __half tWk_hi[DD * DD],  tWk_lo[DD * DD];
__device__ __half tWv_hi[DD * DD],  tWv_lo[DD * DD];
__device__ __half tWo_hi[DD * DD],  tWo_lo[DD * DD];
__device__ __half tW1_hi[FF * DD],  tW1_lo[FF * DD];
__device__ __half tW2_hi[DD * FF],  tW2_lo[DD * FF];

// ---------------- weight transpose + hi/lo split: W[K,N] -> hi/lo [N,K] ------
__global__ __launch_bounds__(256)
void split_transpose(const float* __restrict__ W, __half* __restrict__ hi,
                     __half* __restrict__ lo, int K, int N)
{
    __shared__ float tile[32][33];
    const int tx = threadIdx.x & 31, ty = threadIdx.x >> 5;
    const int kb = blockIdx.y * 32, nb = blockIdx.x * 32;
    #pragma unroll
    for (int i = 0; i < 4; i++)
        tile[ty + i * 8][tx] = W[(size_t)(kb + ty + i * 8) * N + nb + tx];
    __syncthreads();
    #pragma unroll
    for (int i = 0; i < 4; i++) {
        const int n = nb + ty + i * 8, k = kb + tx;
        __half h, l;
        split2h(tile[tx][ty + i * 8], h, l);
        hi[(size_t)n * K + k] = h;
        lo[(size_t)n * K + k] = l;
    }
}

// ---------------- elementwise fp32 -> fp16 (for x) ---------------------------
__global__ __launch_bounds__(256)
void convert_half(const float* __restrict__ in, __half* __restrict__ out)
{
    const int i = (blockIdx.x * 256 + threadIdx.x) * 4;
    float4 v = *reinterpret_cast<const float4*>(in + i);
    __half2 a(__float2half(v.x), __float2half(v.y));
    __half2 b(__float2half(v.z), __float2half(v.w));
    *reinterpret_cast<__half2*>(out + i)     = a;
    *reinterpret_cast<__half2*>(out + i + 2) = b;
}

// ---------------- fp16 2-pass tensor-core GEMM -------------------------------
// C = act(alpha*(A @ B^T + bias));  A [M,K] fp16, B hi/lo [N,K] fp16.
// 2-pass: A*Bh + A*Bl.  BM=BN=128, BK=32, 8 warps x (64x32) warp tiles.
// M%128==0, N%128==0, K%32==0.
#define LDSH 40                      // smem row stride in halves (80B, conflict-free)
#define TILE_B (128 * LDSH * 2)      // 10240B per tile
#define STAGE_B (3 * TILE_B)         // 30720B per stage (A, Bh, Bl)
#define GEMM_SMEM (2 * STAGE_B)      // 61440B

template <int RELU, int HOUT>
__global__ __launch_bounds__(256, 2)
void tc_gemm(const __half* __restrict__ A, const __half* __restrict__ Bh,
             const __half* __restrict__ Bl, const float* __restrict__ bias,
             float* __restrict__ Cf, __half* __restrict__ Ch,
             int M, int N, int K, float alpha)
{
    extern __shared__ __half sm[];
    const uint32_t sb = smem_u32(sm);
    const int tid = threadIdx.x, wid = tid >> 5, lane = tid & 31;
    const int wm = wid & 1, wn = wid >> 1;             // warp tile: rows wm*64, cols wn*32
    const int m0 = blockIdx.y * 128, n0 = blockIdx.x * 128;
    const int nst = K >> 5;

    const __half* srcs[3] = {A, Bh, Bl};

    // ---- async stage loader: 6 x 16B per thread ----
    auto load_stage = [&](int s, int buf) {
        const int k0 = s << 5;
        const uint32_t d0 = sb + buf * STAGE_B;
        #pragma unroll
        for (int i = 0; i < 6; i++) {
            const int tile = i >> 1;                     // 0:A 1:Bh 2:Bl
            const int c = (i & 1) * 256 + tid;           // 0..511
            const int row = c >> 2, part = c & 3;
            const int base_row = (tile == 0) ? m0 : n0;
            const __half* src = srcs[tile] +
                (size_t)(base_row + row) * K + k0 + part * 8;
            const uint32_t dst = d0 + tile * TILE_B + row * (LDSH * 2) + part * 16;
            CP16(dst, src);
        }
        CP_COMMIT();
    };

    float acc[4][4][4];
    #pragma unroll
    for (int i = 0; i < 4; i++)
        #pragma unroll
        for (int j = 0; j < 4; j++)
            #pragma unroll
            for (int q = 0; q < 4; q++) acc[i][j][q] = 0.f;

    load_stage(0, 0);

    // ldmatrix lane addressing (halves)
    const int a_r = (lane & 15), a_c8 = (lane >> 4) * 8;
    const int b_r = ((lane >> 4) & 1) * 8 + (lane & 7);
    const int b_c8 = ((lane >> 3) & 1) * 8;

    #pragma unroll 1
    for (int s = 0; s < nst; s++) {
        const int buf = s & 1;
        if (s + 1 < nst) load_stage(s + 1, buf ^ 1);
        if (s + 1 < nst) { CP_WAIT(1); } else { CP_WAIT(0); }
        __syncthreads();

        const uint32_t ab  = sb + buf * STAGE_B;
        const uint32_t bhb = ab + TILE_B;
        const uint32_t blb = ab + 2 * TILE_B;

        #pragma unroll
        for (int ks = 0; ks < 2; ks++) {
            const int kh = ks * 16;
            uint32_t fA[4][4], fBh[2][4], fBl[2][4];
            #pragma unroll
            for (int i = 0; i < 4; i++) {
                const uint32_t off = ((wm * 64 + i * 16 + a_r) * LDSH + kh + a_c8) * 2;
                LDSM4(fA[i], ab + off);
            }
            #pragma unroll
            for (int j = 0; j < 2; j++) {
                const uint32_t off = ((wn * 32 + j * 16 + b_r) * LDSH + kh + b_c8) * 2;
                LDSM4(fBh[j], bhb + off);
                LDSM4(fBl[j], blb + off);
            }
            #pragma unroll
            for (int n = 0; n < 4; n++) {
                const int j = n >> 1, h = (n & 1) * 2;
                const uint32_t bh0 = fBh[j][h], bh1 = fBh[j][h + 1];
                const uint32_t bl0 = fBl[j][h], bl1 = fBl[j][h + 1];
                #pragma unroll
                for (int i = 0; i < 4; i++) {
                    MMA_F16(acc[i][n], fA[i], bh0, bh1);
                    MMA_F16(acc[i][n], fA[i], bl0, bl1);
                }
            }
        }
        __syncthreads();
    }

    // ---- epilogue ----
    const int row0 = m0 + wm * 64 + (lane >> 2);
    const int col0 = n0 + wn * 32 + (lane & 3) * 2;
    #pragma unroll
    for (int i = 0; i < 4; i++) {
        #pragma unroll
        for (int j = 0; j < 4; j++) {
            const int r = row0 + i * 16;
            const int c = col0 + j * 8;
            const float b0 = bias[c], b1 = bias[c + 1];
            float v0 = alpha * (acc[i][j][0] + b0);
            float v1 = alpha * (acc[i][j][1] + b1);
            float v2 = alpha * (acc[i][j][2] + b0);
            float v3 = alpha * (acc[i][j][3] + b1);
            if (RELU) {
                v0 = fmaxf(v0, 0.f); v1 = fmaxf(v1, 0.f);
                v2 = fmaxf(v2, 0.f); v3 = fmaxf(v3, 0.f);
            }
            if (!HOUT) {
                *reinterpret_cast<float2*>(Cf + (size_t)r * N + c)       = make_float2(v0, v1);
                *reinterpret_cast<float2*>(Cf + (size_t)(r + 8) * N + c) = make_float2(v2, v3);
            } else {
                *reinterpret_cast<__half2*>(Ch + (size_t)r * N + c) =
                    __half2(__float2half(v0), __float2half(v1));
                *reinterpret_cast<__half2*>(Ch + (size_t)(r + 8) * N + c) =
                    __half2(__float2half(v2), __float2half(v3));
            }
        }
    }
}

// ---------------- LayerNorm over D=768 (optional fp16 side output) -----------
__global__ __launch_bounds__(256)
void ln_kernel(const float* __restrict__ a, const float* __restrict__ r,
               const float* __restrict__ gamma, const float* __restrict__ beta,
               float* __restrict__ out, __half* __restrict__ oh, int mode)
{
    const int row = blockIdx.x;
    const int t = threadIdx.x;
    const float* ap = a + (size_t)row * DD;

    float x[3];
    #pragma unroll
    for (int j = 0; j < 3; j++) {
        const int idx = t + j * 256;
        float val = ap[idx];
        if (mode == 0)      val = 2.f * val;
        else if (mode == 1) val += r[(size_t)(row & (GG - 1)) * DD + idx];
        else                val += r[(size_t)row * DD + idx];
        x[j] = val;
    }
    float s1 = x[0] + x[1] + x[2];
    float s2 = x[0] * x[0] + x[1] * x[1] + x[2] * x[2];
    #pragma unroll
    for (int off = 16; off; off >>= 1) {
        s1 += __shfl_xor_sync(0xffffffffu, s1, off);
        s2 += __shfl_xor_sync(0xffffffffu, s2, off);
    }
    __shared__ float sh1[8], sh2[8];
    const int w = t >> 5, lane = t & 31;
    if (lane == 0) { sh1[w] = s1; sh2[w] = s2; }
    __syncthreads();
    float S1 = 0.f, S2 = 0.f;
    #pragma unroll
    for (int i = 0; i < 8; i++) { S1 += sh1[i]; S2 += sh2[i]; }
    const float mean = S1 * (1.f / (float)DD);
    const float var  = S2 * (1.f / (float)DD) - mean * mean;
    const float rstd = rsqrtf(var + 1e-5f);

    #pragma unroll
    for (int j = 0; j < 3; j++) {
        const int idx = t + j * 256;
        const float v = (x[j] - mean) * rstd * gamma[idx] + beta[idx];
        out[(size_t)row * DD + idx] = v;
        if (oh) oh[(size_t)row * DD + idx] = __float2half(v);
    }
}

// ---------------- fused cross-attention, fp16 output -------------------------
__global__ __launch_bounds__(256)
void attn_kernel(const float* __restrict__ q, const float* __restrict__ k,
                 const float* __restrict__ v, __half* __restrict__ oh)
{
    __shared__ float ks[NN][HD];
    __shared__ float vs[NN][HD];
    const int h = blockIdx.x, b = blockIdx.y;
    const int t = threadIdx.x;

    for (int i = t; i < NN * HD; i += 256) {
        const int n = i / HD, d = i % HD;
        const size_t gi = ((size_t)(b * NN + n)) * DD + h * HD + d;
        ks[n][d] = k[gi];
        vs[n][d] = v[gi];
    }
    __syncthreads();

    const int g = t;
    float4 qv[HD / 4];
    const float4* qp = reinterpret_cast<const float4*>(q + (size_t)g * DD + h * HD);
    #pragma unroll
    for (int i = 0; i < HD / 4; i++) qv[i] = qp[i];

    float s[NN];
    #pragma unroll 7
    for (int n = 0; n < NN; n++) {
        const float4* kp = reinterpret_cast<const float4*>(ks[n]);
        float acc = 0.f;
        #pragma unroll
        for (int i = 0; i < HD / 4; i++) {
            float4 kk = kp[i];
            acc += qv[i].x * kk.x + qv[i].y * kk.y + qv[i].z * kk.z + qv[i].w * kk.w;
        }
        s[n] = acc;
    }
    float m = -1e30f;
    #pragma unroll
    for (int n = 0; n < NN; n++) m = fmaxf(m, s[n]);
    float sum = 0.f;
    #pragma unroll
    for (int n = 0; n < NN; n++) { s[n] = __expf(s[n] - m); sum += s[n]; }
    const float inv = 1.f / sum;

    const size_t ob = ((size_t)(b * GG + g)) * DD + h * HD;
    #pragma unroll
    for (int d4 = 0; d4 < HD / 4; d4++) {
        float4 acc = {0.f, 0.f, 0.f, 0.f};
        #pragma unroll 7
        for (int n = 0; n < NN; n++) {
            const float p = s[n];
            float4 vv = *reinterpret_cast<const float4*>(&vs[n][d4 * 4]);
            acc.x += p * vv.x; acc.y += p * vv.y; acc.z += p * vv.z; acc.w += p * vv.w;
        }
        acc.x *= inv; acc.y *= inv; acc.z *= inv; acc.w *= inv;
        *reinterpret_cast<__half2*>(oh + ob + d4 * 4) =
            __half2(__float2half(acc.x), __float2half(acc.y));
        *reinterpret_cast<__half2*>(oh + ob + d4 * 4 + 2) =
            __half2(__float2half(acc.z), __float2half(acc.w));
    }
}

// ---------------- GroupFC ----------------------------------------------------
__global__ __launch_bounds__(256)
void groupfc_kernel(const float* __restrict__ h, const float* __restrict__ Wg,
                    const float* __restrict__ bg, float* __restrict__ out)
{
    const int g  = blockIdx.y;
    const int b0 = blockIdx.x * 64;
    __shared__ float hs[32][65];
    __shared__ float ws[32][65];
    const int t = threadIdx.x;
    const int tx = (t % 16) * 4;
    const int ty = (t / 16) * 4;
    float acc[4][4] = {};

    for (int d0 = 0; d0 < DD; d0 += 32) {
        for (int i = t; i < 64 * 32; i += 256) {
            const int bi = i / 32, di = i % 32;
            hs[di][bi] = h[((size_t)(b0 + bi) * GG + g) * DD + d0 + di];
        }
        for (int i = t; i < 32 * 64; i += 256) {
            const int di = i / 64, fi = i % 64;
            ws[di][fi] = (fi < DUP) ? Wg[((size_t)g * DD + d0 + di) * DUP + fi] : 0.f;
        }
        __syncthreads();
        #pragma unroll
        for (int d = 0; d < 32; d++) {
            float rh[4], rb[4];
            #pragma unroll
            for (int i = 0; i < 4; i++) rh[i] = hs[d][ty + i];
            #pragma unroll
            for (int j = 0; j < 4; j++) rb[j] = ws[d][tx + j];
            #pragma unroll
            for (int i = 0; i < 4; i++)
                #pragma unroll
                for (int j = 0; j < 4; j++)
                    acc[i][j] += rh[i] * rb[j];
        }
        __syncthreads();
    }
    #pragma unroll
    for (int i = 0; i < 4; i++) {
        #pragma unroll
        for (int j = 0; j < 4; j++) {
            const int f = tx + j;
            if (f < DUP) {
                const int c = g * DUP + f;
                if (c < NCLS)
                    out[(size_t)(b0 + ty + i) * NCLS + c] = acc[i][j] + bg[c];
            }
        }
    }
}

// ---------------- launch -----------------------------------------------------
static float* sym(const void* s) { void* p = nullptr; cudaGetSymbolAddress(&p, s); return (float*)p; }
static __half* symh(const void* s) { void* p = nullptr; cudaGetSymbolAddress(&p, s); return (__half*)p; }

extern "C" void kernel_launch(void* const* d_in, const int* in_sizes, int n_in,
                              void* d_out, int out_size)
{
    (void)in_sizes; (void)n_in; (void)out_size;
    const float* x      = (const float*)d_in[0];
    const float* We     = (const float*)d_in[1];
    const float* be     = (const float*)d_in[2];
    const float* query  = (const float*)d_in[3];
    const float* Wq     = (const float*)d_in[4];
    const float* bq     = (const float*)d_in[5];
    const float* Wk     = (const float*)d_in[6];
    const float* bk     = (const float*)d_in[7];
    const float* Wv     = (const float*)d_in[8];
    const float* bv     = (const float*)d_in[9];
    const float* Wo     = (const float*)d_in[10];
    const float* bo     = (const float*)d_in[11];
    const float* g1     = (const float*)d_in[12];
    const float* beta1  = (const float*)d_in[13];
    const float* g2     = (const float*)d_in[14];
    const float* beta2  = (const float*)d_in[15];
    const float* g3     = (const float*)d_in[16];
    const float* beta3  = (const float*)d_in[17];
    const float* W1     = (const float*)d_in[18];
    const float* b1     = (const float*)d_in[19];
    const float* W2     = (const float*)d_in[20];
    const float* b2     = (const float*)d_in[21];
    const float* Wg     = (const float*)d_in[22];
    const float* bg     = (const float*)d_in[23];
    float* out = (float*)d_out;

    float *p_k = sym(g_k), *p_v = sym(g_v), *p_t1 = sym(g_t1), *p_q = sym(g_q);
    float *p_oproj = sym(g_oproj), *p_t2 = sym(g_t2), *p_ffn2 = sym(g_ffn2);
    __half *p_xh = symh(g_xh), *p_mh = symh(g_mh), *p_t1h = symh(g_t1h);
    __half *p_aoh = symh(g_aoh), *p_t2h = symh(g_t2h), *p_ffh = symh(g_ffh);
    __half *pWe_h = symh(tWe_hi), *pWe_l = symh(tWe_lo);
    __half *pWq_h = symh(tWq_hi), *pWq_l = symh(tWq_lo);
    __half *pWk_h = symh(tWk_hi), *pWk_l = symh(tWk_lo);
    __half *pWv_h = symh(tWv_hi), *pWv_l = symh(tWv_lo);
    __half *pWo_h = symh(tWo_hi), *pWo_l = symh(tWo_lo);
    __half *pW1_h = symh(tW1_hi), *pW1_l = symh(tW1_lo);
    __half *pW2_h = symh(tW2_hi), *pW2_l = symh(tW2_lo);

    cudaFuncSetAttribute(tc_gemm<0, 0>, cudaFuncAttributeMaxDynamicSharedMemorySize, GEMM_SMEM);
    cudaFuncSetAttribute(tc_gemm<0, 1>, cudaFuncAttributeMaxDynamicSharedMemorySize, GEMM_SMEM);
    cudaFuncSetAttribute(tc_gemm<1, 1>, cudaFuncAttributeMaxDynamicSharedMemorySize, GEMM_SMEM);

    const float qscale = 0.10206207261596577f;  // 1/sqrt(96)

    // weight transpose + fp16 hi/lo split
    split_transpose<<<dim3(DD / 32, CIN / 32), 256>>>(We, pWe_h, pWe_l, CIN, DD);
    split_transpose<<<dim3(DD / 32, DD / 32), 256>>>(Wq, pWq_h, pWq_l, DD, DD);
    split_transpose<<<dim3(DD / 32, DD / 32), 256>>>(Wk, pWk_h, pWk_l, DD, DD);
    split_transpose<<<dim3(DD / 32, DD / 32), 256>>>(Wv, pWv_h, pWv_l, DD, DD);
    split_transpose<<<dim3(DD / 32, DD / 32), 256>>>(Wo, pWo_h, pWo_l, DD, DD);
    split_transpose<<<dim3(FF / 32, DD / 32), 256>>>(W1, pW1_h, pW1_l, DD, FF);
    split_transpose<<<dim3(DD / 32, FF / 32), 256>>>(W2, pW2_h, pW2_l, FF, DD);
    // x -> fp16
    convert_half<<<(BB * NN * CIN) / 1024, 256>>>(x, p_xh);

    // t1 = LN(2*query) (+fp16); q = (t1@Wq + bq)/sqrt(96)
    ln_kernel<<<GG, 256>>>(query, nullptr, g1, beta1, p_t1, p_t1h, 0);
    tc_gemm<0, 0><<<dim3(DD / 128, GG / 128), 256, GEMM_SMEM>>>(
        p_t1h, pWq_h, pWq_l, bq, p_q, nullptr, GG, DD, DD, qscale);

    // mem = relu(x @ We + be)  -> fp16 directly
    tc_gemm<1, 1><<<dim3(DD / 128, (BB * NN) / 128), 256, GEMM_SMEM>>>(
        p_xh, pWe_h, pWe_l, be, nullptr, p_mh, BB * NN, DD, CIN, 1.f);
    // k, v projections (fp32 out for attention)
    tc_gemm<0, 0><<<dim3(DD / 128, (BB * NN) / 128), 256, GEMM_SMEM>>>(
        p_mh, pWk_h, pWk_l, bk, p_k, nullptr, BB * NN, DD, DD, 1.f);
    tc_gemm<0, 0><<<dim3(DD / 128, (BB * NN) / 128), 256, GEMM_SMEM>>>(
        p_mh, pWv_h, pWv_l, bv, p_v, nullptr, BB * NN, DD, DD, 1.f);

    // fused attention -> fp16
    attn_kernel<<<dim3(HH, BB), 256>>>(p_q, p_k, p_v, p_aoh);

    // output projection + residual LN (t2 fp32 + fp16)
    tc_gemm<0, 0><<<dim3(DD / 128, (BB * GG) / 128), 256, GEMM_SMEM>>>(
        p_aoh, pWo_h, pWo_l, bo, p_oproj, nullptr, BB * GG, DD, DD, 1.f);
    ln_kernel<<<BB * GG, 256>>>(p_oproj, p_t1, g2, beta2, p_t2, p_t2h, 1);

    // FFN: ff = relu(t2@W1+b1) -> fp16; ffn2 = ff@W2+b2 -> fp32
    tc_gemm<1, 1><<<dim3(FF / 128, (BB * GG) / 128), 256, GEMM_SMEM>>>(
        p_t2h, pW1_h, pW1_l, b1, nullptr, p_ffh, BB * GG, FF, DD, 1.f);
    tc_gemm<0, 0><<<dim3(DD / 128, (BB * GG) / 128), 256, GEMM_SMEM>>>(
        p_ffh, pW2_h, pW2_l, b2, p_ffn2, nullptr, BB * GG, DD, FF, 1.f);
    ln_kernel<<<BB * GG, 256>>>(p_ffn2, p_t2, g3, beta3, p_oproj, nullptr, 2);

    // GroupFC
    groupfc_kernel<<<dim3(BB / 64, GG), 256>>>(p_oproj, Wg, bg, out);
}

// round 8
// speedup vs baseline: 4.2071x; 1.3667x over previous
#include <cuda_runtime.h>
#include <cuda_fp16.h>
#include <math.h>
#include <stdint.h>

// ---------------- problem constants ----------------
#define BB 128      // batch
#define NN 49       // spatial tokens
#define CIN 2048
#define GG 256      // query groups
#define DD 768      // model dim
#define HH 8        // heads
#define HD 96       // head dim
#define FF 2048
#define NCLS 12547
#define DUP 50

// ---------------- asm helpers (sm_80+ features only) -------------------------
__device__ __forceinline__ uint32_t smem_u32(const void* p) {
    uint32_t a;
    asm("{ .reg .u64 t; cvta.to.shared.u64 t, %1; cvt.u32.u64 %0, t; }" : "=r"(a) : "l"(p));
    return a;
}
#define CP16(dst, src) \
    asm volatile("cp.async.cg.shared.global [%0], [%1], 16;" :: "r"(dst), "l"(src))
#define CP_COMMIT() asm volatile("cp.async.commit_group;" ::: "memory")
#define CP_WAIT(n)  asm volatile("cp.async.wait_group %0;" :: "n"(n) : "memory")
#define LDSM4(r, addr) \
    asm volatile("ldmatrix.sync.aligned.m8n8.x4.shared.b16 {%0,%1,%2,%3}, [%4];" \
                 : "=r"((r)[0]), "=r"((r)[1]), "=r"((r)[2]), "=r"((r)[3]) : "r"(addr))
#define MMA_F16(c, a, b0, b1) \
    asm volatile("mma.sync.aligned.m16n8k16.row.col.f32.f16.f16.f32 " \
                 "{%0,%1,%2,%3},{%4,%5,%6,%7},{%8,%9},{%0,%1,%2,%3};" \
                 : "+f"((c)[0]), "+f"((c)[1]), "+f"((c)[2]), "+f"((c)[3]) \
                 : "r"((a)[0]), "r"((a)[1]), "r"((a)[2]), "r"((a)[3]), "r"(b0), "r"(b1))

// ---------------- scratch (device globals) -----------------------------------
// fp32
__device__ float g_k    [BB * NN * DD];
__device__ float g_v    [BB * NN * DD];
__device__ float g_t1   [GG * DD];
__device__ float g_q    [GG * DD];
__device__ float g_oproj[BB * GG * DD];   // Wo out; later reused as h
__device__ float g_t2   [BB * GG * DD];
__device__ float g_ffn2 [BB * GG * DD];
// fp16 activation operands
__device__ __half g_xh [BB * NN * CIN];
__device__ __half g_mh [BB * NN * DD];
__device__ __half g_t1h[GG * DD];
__device__ __half g_aoh[BB * GG * DD];
__device__ __half g_t2h[BB * GG * DD];
__device__ __half g_ffh[BB * GG * FF];
// transposed fp16 weights: [N,K]
__device__ __half tWe[DD * CIN];
__device__ __half tWq[DD * DD];
__device__ __half tWk[DD * DD];
__device__ __half tWv[DD * DD];
__device__ __half tWo[DD * DD];
__device__ __half tW1[FF * DD];
__device__ __half tW2[DD * FF];

// ---------------- weight transpose: W[K,N] fp32 -> [N,K] fp16 ----------------
__global__ __launch_bounds__(256)
void transpose_half(const float* __restrict__ W, __half* __restrict__ o,
                    int K, int N)
{
    __shared__ float tile[32][33];
    const int tx = threadIdx.x & 31, ty = threadIdx.x >> 5;
    const int kb = blockIdx.y * 32, nb = blockIdx.x * 32;
    #pragma unroll
    for (int i = 0; i < 4; i++)
        tile[ty + i * 8][tx] = W[(size_t)(kb + ty + i * 8) * N + nb + tx];
    __syncthreads();
    #pragma unroll
    for (int i = 0; i < 4; i++) {
        const int n = nb + ty + i * 8, k = kb + tx;
        o[(size_t)n * K + k] = __float2half(tile[tx][ty + i * 8]);
    }
}

// ---------------- elementwise fp32 -> fp16 (for x) ---------------------------
__global__ __launch_bounds__(256)
void convert_half(const float* __restrict__ in, __half* __restrict__ out)
{
    const int i = (blockIdx.x * 256 + threadIdx.x) * 4;
    float4 v = *reinterpret_cast<const float4*>(in + i);
    __half2 a(__float2half(v.x), __float2half(v.y));
    __half2 b(__float2half(v.z), __float2half(v.w));
    *reinterpret_cast<__half2*>(out + i)     = a;
    *reinterpret_cast<__half2*>(out + i + 2) = b;
}

// ---------------- fp16 single-pass tensor-core GEMM --------------------------
// C = act(alpha*(A @ B^T + bias));  A [M,K] fp16, B [N,K] fp16.
// BM=BN=128, BK=32, 8 warps x (64x32) warp tiles.  M%128==0, N%128==0, K%32==0.
#define LDSH 40                      // smem row stride in halves (80B, conflict-free)
#define TILE_B (128 * LDSH * 2)      // 10240B per tile
#define STAGE_B (2 * TILE_B)         // 20480B per stage (A, B)
#define GEMM_SMEM (2 * STAGE_B)      // 40960B

template <int RELU, int HOUT>
__global__ __launch_bounds__(256, 2)
void tc_gemm(const __half* __restrict__ A, const __half* __restrict__ B,
             const float* __restrict__ bias,
             float* __restrict__ Cf, __half* __restrict__ Ch,
             int M, int N, int K, float alpha)
{
    extern __shared__ __half sm[];
    const uint32_t sb = smem_u32(sm);
    const int tid = threadIdx.x, wid = tid >> 5, lane = tid & 31;
    const int wm = wid & 1, wn = wid >> 1;             // warp tile: rows wm*64, cols wn*32
    const int m0 = blockIdx.y * 128, n0 = blockIdx.x * 128;
    const int nst = K >> 5;

    // ---- async stage loader: 4 x 16B per thread ----
    auto load_stage = [&](int s, int buf) {
        const int k0 = s << 5;
        const uint32_t d0 = sb + buf * STAGE_B;
        #pragma unroll
        for (int i = 0; i < 4; i++) {
            const int isA = (i < 2);
            const int c = (i & 1) * 256 + tid;           // 0..511
            const int row = c >> 2, part = c & 3;
            const __half* src = (isA ? A + (size_t)(m0 + row) * K
                                     : B + (size_t)(n0 + row) * K) + k0 + part * 8;
            const uint32_t dst = d0 + (isA ? 0 : TILE_B) + row * (LDSH * 2) + part * 16;
            CP16(dst, src);
        }
        CP_COMMIT();
    };

    float acc[4][4][4];
    #pragma unroll
    for (int i = 0; i < 4; i++)
        #pragma unroll
        for (int j = 0; j < 4; j++)
            #pragma unroll
            for (int q = 0; q < 4; q++) acc[i][j][q] = 0.f;

    load_stage(0, 0);

    // ldmatrix lane addressing (halves)
    const int a_r = (lane & 15), a_c8 = (lane >> 4) * 8;
    const int b_r = ((lane >> 4) & 1) * 8 + (lane & 7);
    const int b_c8 = ((lane >> 3) & 1) * 8;

    #pragma unroll 1
    for (int s = 0; s < nst; s++) {
        const int buf = s & 1;
        if (s + 1 < nst) load_stage(s + 1, buf ^ 1);
        if (s + 1 < nst) { CP_WAIT(1); } else { CP_WAIT(0); }
        __syncthreads();

        const uint32_t ab = sb + buf * STAGE_B;
        const uint32_t bb = ab + TILE_B;

        #pragma unroll
        for (int ks = 0; ks < 2; ks++) {
            const int kh = ks * 16;
            uint32_t fA[4][4], fB[2][4];
            #pragma unroll
            for (int i = 0; i < 4; i++) {
                const uint32_t off = ((wm * 64 + i * 16 + a_r) * LDSH + kh + a_c8) * 2;
                LDSM4(fA[i], ab + off);
            }
            #pragma unroll
            for (int j = 0; j < 2; j++) {
                const uint32_t off = ((wn * 32 + j * 16 + b_r) * LDSH + kh + b_c8) * 2;
                LDSM4(fB[j], bb + off);
            }
            #pragma unroll
            for (int n = 0; n < 4; n++) {
                const int j = n >> 1, h = (n & 1) * 2;
                const uint32_t b0 = fB[j][h], b1 = fB[j][h + 1];
                #pragma unroll
                for (int i = 0; i < 4; i++)
                    MMA_F16(acc[i][n], fA[i], b0, b1);
            }
        }
        __syncthreads();
    }

    // ---- epilogue ----
    const int row0 = m0 + wm * 64 + (lane >> 2);
    const int col0 = n0 + wn * 32 + (lane & 3) * 2;
    #pragma unroll
    for (int i = 0; i < 4; i++) {
        #pragma unroll
        for (int j = 0; j < 4; j++) {
            const int r = row0 + i * 16;
            const int c = col0 + j * 8;
            const float b0 = bias[c], b1 = bias[c + 1];
            float v0 = alpha * (acc[i][j][0] + b0);
            float v1 = alpha * (acc[i][j][1] + b1);
            float v2 = alpha * (acc[i][j][2] + b0);
            float v3 = alpha * (acc[i][j][3] + b1);
            if (RELU) {
                v0 = fmaxf(v0, 0.f); v1 = fmaxf(v1, 0.f);
                v2 = fmaxf(v2, 0.f); v3 = fmaxf(v3, 0.f);
            }
            if (!HOUT) {
                *reinterpret_cast<float2*>(Cf + (size_t)r * N + c)       = make_float2(v0, v1);
                *reinterpret_cast<float2*>(Cf + (size_t)(r + 8) * N + c) = make_float2(v2, v3);
            } else {
                *reinterpret_cast<__half2*>(Ch + (size_t)r * N + c) =
                    __half2(__float2half(v0), __float2half(v1));
                *reinterpret_cast<__half2*>(Ch + (size_t)(r + 8) * N + c) =
                    __half2(__float2half(v2), __float2half(v3));
            }
        }
    }
}

// ---------------- LayerNorm over D=768 (optional fp16 side output) -----------
__global__ __launch_bounds__(256)
void ln_kernel(const float* __restrict__ a, const float* __restrict__ r,
               const float* __restrict__ gamma, const float* __restrict__ beta,
               float* __restrict__ out, __half* __restrict__ oh, int mode)
{
    const int row = blockIdx.x;
    const int t = threadIdx.x;
    const float* ap = a + (size_t)row * DD;

    float x[3];
    #pragma unroll
    for (int j = 0; j < 3; j++) {
        const int idx = t + j * 256;
        float val = ap[idx];
        if (mode == 0)      val = 2.f * val;
        else if (mode == 1) val += r[(size_t)(row & (GG - 1)) * DD + idx];
        else                val += r[(size_t)row * DD + idx];
        x[j] = val;
    }
    float s1 = x[0] + x[1] + x[2];
    float s2 = x[0] * x[0] + x[1] * x[1] + x[2] * x[2];
    #pragma unroll
    for (int off = 16; off; off >>= 1) {
        s1 += __shfl_xor_sync(0xffffffffu, s1, off);
        s2 += __shfl_xor_sync(0xffffffffu, s2, off);
    }
    __shared__ float sh1[8], sh2[8];
    const int w = t >> 5, lane = t & 31;
    if (lane == 0) { sh1[w] = s1; sh2[w] = s2; }
    __syncthreads();
    float S1 = 0.f, S2 = 0.f;
    #pragma unroll
    for (int i = 0; i < 8; i++) { S1 += sh1[i]; S2 += sh2[i]; }
    const float mean = S1 * (1.f / (float)DD);
    const float var  = S2 * (1.f / (float)DD) - mean * mean;
    const float rstd = rsqrtf(var + 1e-5f);

    #pragma unroll
    for (int j = 0; j < 3; j++) {
        const int idx = t + j * 256;
        const float v = (x[j] - mean) * rstd * gamma[idx] + beta[idx];
        out[(size_t)row * DD + idx] = v;
        if (oh) oh[(size_t)row * DD + idx] = __float2half(v);
    }
}

// ---------------- fused cross-attention, fp16 output -------------------------
__global__ __launch_bounds__(256)
void attn_kernel(const float* __restrict__ q, const float* __restrict__ k,
                 const float* __restrict__ v, __half* __restrict__ oh)
{
    __shared__ float ks[NN][HD];
    __shared__ float vs[NN][HD];
    const int h = blockIdx.x, b = blockIdx.y;
    const int t = threadIdx.x;

    for (int i = t; i < NN * HD; i += 256) {
        const int n = i / HD, d = i % HD;
        const size_t gi = ((size_t)(b * NN + n)) * DD + h * HD + d;
        ks[n][d] = k[gi];
        vs[n][d] = v[gi];
    }
    __syncthreads();

    const int g = t;
    float4 qv[HD / 4];
    const float4* qp = reinterpret_cast<const float4*>(q + (size_t)g * DD + h * HD);
    #pragma unroll
    for (int i = 0; i < HD / 4; i++) qv[i] = qp[i];

    float s[NN];
    #pragma unroll 7
    for (int n = 0; n < NN; n++) {
        const float4* kp = reinterpret_cast<const float4*>(ks[n]);
        float acc = 0.f;
        #pragma unroll
        for (int i = 0; i < HD / 4; i++) {
            float4 kk = kp[i];
            acc += qv[i].x * kk.x + qv[i].y * kk.y + qv[i].z * kk.z + qv[i].w * kk.w;
        }
        s[n] = acc;
    }
    float m = -1e30f;
    #pragma unroll
    for (int n = 0; n < NN; n++) m = fmaxf(m, s[n]);
    float sum = 0.f;
    #pragma unroll
    for (int n = 0; n < NN; n++) { s[n] = __expf(s[n] - m); sum += s[n]; }
    const float inv = 1.f / sum;

    const size_t ob = ((size_t)(b * GG + g)) * DD + h * HD;
    #pragma unroll
    for (int d4 = 0; d4 < HD / 4; d4++) {
        float4 acc = {0.f, 0.f, 0.f, 0.f};
        #pragma unroll 7
        for (int n = 0; n < NN; n++) {
            const float p = s[n];
            float4 vv = *reinterpret_cast<const float4*>(&vs[n][d4 * 4]);
            acc.x += p * vv.x; acc.y += p * vv.y; acc.z += p * vv.z; acc.w += p * vv.w;
        }
        acc.x *= inv; acc.y *= inv; acc.z *= inv; acc.w *= inv;
        *reinterpret_cast<__half2*>(oh + ob + d4 * 4) =
            __half2(__float2half(acc.x), __float2half(acc.y));
        *reinterpret_cast<__half2*>(oh + ob + d4 * 4 + 2) =
            __half2(__float2half(acc.z), __float2half(acc.w));
    }
}

// ---------------- GroupFC ----------------------------------------------------
__global__ __launch_bounds__(256)
void groupfc_kernel(const float* __restrict__ h, const float* __restrict__ Wg,
                    const float* __restrict__ bg, float* __restrict__ out)
{
    const int g  = blockIdx.y;
    const int b0 = blockIdx.x * 64;
    __shared__ float hs[32][65];
    __shared__ float ws[32][65];
    const int t = threadIdx.x;
    const int tx = (t % 16) * 4;
    const int ty = (t / 16) * 4;
    float acc[4][4] = {};

    for (int d0 = 0; d0 < DD; d0 += 32) {
        for (int i = t; i < 64 * 32; i += 256) {
            const int bi = i / 32, di = i % 32;
            hs[di][bi] = h[((size_t)(b0 + bi) * GG + g) * DD + d0 + di];
        }
        for (int i = t; i < 32 * 64; i += 256) {
            const int di = i / 64, fi = i % 64;
            ws[di][fi] = (fi < DUP) ? Wg[((size_t)g * DD + d0 + di) * DUP + fi] : 0.f;
        }
        __syncthreads();
        #pragma unroll
        for (int d = 0; d < 32; d++) {
            float rh[4], rb[4];
            #pragma unroll
            for (int i = 0; i < 4; i++) rh[i] = hs[d][ty + i];
            #pragma unroll
            for (int j = 0; j < 4; j++) rb[j] = ws[d][tx + j];
            #pragma unroll
            for (int i = 0; i < 4; i++)
                #pragma unroll
                for (int j = 0; j < 4; j++)
                    acc[i][j] += rh[i] * rb[j];
        }
        __syncthreads();
    }
    #pragma unroll
    for (int i = 0; i < 4; i++) {
        #pragma unroll
        for (int j = 0; j < 4; j++) {
            const int f = tx + j;
            if (f < DUP) {
                const int c = g * DUP + f;
                if (c < NCLS)
                    out[(size_t)(b0 + ty + i) * NCLS + c] = acc[i][j] + bg[c];
            }
        }
    }
}

// ---------------- launch -----------------------------------------------------
static float* sym(const void* s) { void* p = nullptr; cudaGetSymbolAddress(&p, s); return (float*)p; }
static __half* symh(const void* s) { void* p = nullptr; cudaGetSymbolAddress(&p, s); return (__half*)p; }

extern "C" void kernel_launch(void* const* d_in, const int* in_sizes, int n_in,
                              void* d_out, int out_size)
{
    (void)in_sizes; (void)n_in; (void)out_size;
    const float* x      = (const float*)d_in[0];
    const float* We     = (const float*)d_in[1];
    const float* be     = (const float*)d_in[2];
    const float* query  = (const float*)d_in[3];
    const float* Wq     = (const float*)d_in[4];
    const float* bq     = (const float*)d_in[5];
    const float* Wk     = (const float*)d_in[6];
    const float* bk     = (const float*)d_in[7];
    const float* Wv     = (const float*)d_in[8];
    const float* bv     = (const float*)d_in[9];
    const float* Wo     = (const float*)d_in[10];
    const float* bo     = (const float*)d_in[11];
    const float* g1     = (const float*)d_in[12];
    const float* beta1  = (const float*)d_in[13];
    const float* g2     = (const float*)d_in[14];
    const float* beta2  = (const float*)d_in[15];
    const float* g3     = (const float*)d_in[16];
    const float* beta3  = (const float*)d_in[17];
    const float* W1     = (const float*)d_in[18];
    const float* b1     = (const float*)d_in[19];
    const float* W2     = (const float*)d_in[20];
    const float* b2     = (const float*)d_in[21];
    const float* Wg     = (const float*)d_in[22];
    const float* bg     = (const float*)d_in[23];
    float* out = (float*)d_out;

    float *p_k = sym(g_k), *p_v = sym(g_v), *p_t1 = sym(g_t1), *p_q = sym(g_q);
    float *p_oproj = sym(g_oproj), *p_t2 = sym(g_t2), *p_ffn2 = sym(g_ffn2);
    __half *p_xh = symh(g_xh), *p_mh = symh(g_mh), *p_t1h = symh(g_t1h);
    __half *p_aoh = symh(g_aoh), *p_t2h = symh(g_t2h), *p_ffh = symh(g_ffh);
    __half *pWe = symh(tWe), *pWq = symh(tWq), *pWk = symh(tWk), *pWv = symh(tWv);
    __half *pWo = symh(tWo), *pW1 = symh(tW1), *pW2 = symh(tW2);

    cudaFuncSetAttribute(tc_gemm<0, 0>, cudaFuncAttributeMaxDynamicSharedMemorySize, GEMM_SMEM);
    cudaFuncSetAttribute(tc_gemm<0, 1>, cudaFuncAttributeMaxDynamicSharedMemorySize, GEMM_SMEM);
    cudaFuncSetAttribute(tc_gemm<1, 1>, cudaFuncAttributeMaxDynamicSharedMemorySize, GEMM_SMEM);

    const float qscale = 0.10206207261596577f;  // 1/sqrt(96)

    // weight transpose -> fp16 [N,K]
    transpose_half<<<dim3(DD / 32, CIN / 32), 256>>>(We, pWe, CIN, DD);
    transpose_half<<<dim3(DD / 32, DD / 32), 256>>>(Wq, pWq, DD, DD);
    transpose_half<<<dim3(DD / 32, DD / 32), 256>>>(Wk, pWk, DD, DD);
    transpose_half<<<dim3(DD / 32, DD / 32), 256>>>(Wv, pWv, DD, DD);
    transpose_half<<<dim3(DD / 32, DD / 32), 256>>>(Wo, pWo, DD, DD);
    transpose_half<<<dim3(FF / 32, DD / 32), 256>>>(W1, pW1, DD, FF);
    transpose_half<<<dim3(DD / 32, FF / 32), 256>>>(W2, pW2, FF, DD);
    // x -> fp16
    convert_half<<<(BB * NN * CIN) / 1024, 256>>>(x, p_xh);

    // t1 = LN(2*query) (+fp16); q = (t1@Wq + bq)/sqrt(96)
    ln_kernel<<<GG, 256>>>(query, nullptr, g1, beta1, p_t1, p_t1h, 0);
    tc_gemm<0, 0><<<dim3(DD / 128, GG / 128), 256, GEMM_SMEM>>>(
        p_t1h, pWq, bq, p_q, nullptr, GG, DD, DD, qscale);

    // mem = relu(x @ We + be)  -> fp16 directly
    tc_gemm<1, 1><<<dim3(DD / 128, (BB * NN) / 128), 256, GEMM_SMEM>>>(
        p_xh, pWe, be, nullptr, p_mh, BB * NN, DD, CIN, 1.f);
    // k, v projections (fp32 out for attention)
    tc_gemm<0, 0><<<dim3(DD / 128, (BB * NN) / 128), 256, GEMM_SMEM>>>(
        p_mh, pWk, bk, p_k, nullptr, BB * NN, DD, DD, 1.f);
    tc_gemm<0, 0><<<dim3(DD / 128, (BB * NN) / 128), 256, GEMM_SMEM>>>(
        p_mh, pWv, bv, p_v, nullptr, BB * NN, DD, DD, 1.f);

    // fused attention -> fp16
    attn_kernel<<<dim3(HH, BB), 256>>>(p_q, p_k, p_v, p_aoh);

    // output projection + residual LN (t2 fp32 + fp16)
    tc_gemm<0, 0><<<dim3(DD / 128, (BB * GG) / 128), 256, GEMM_SMEM>>>(
        p_aoh, pWo, bo, p_oproj, nullptr, BB * GG, DD, DD, 1.f);
    ln_kernel<<<BB * GG, 256>>>(p_oproj, p_t1, g2, beta2, p_t2, p_t2h, 1);

    // FFN: ff = relu(t2@W1+b1) -> fp16; ffn2 = ff@W2+b2 -> fp32
    tc_gemm<1, 1><<<dim3(FF / 128, (BB * GG) / 128), 256, GEMM_SMEM>>>(
        p_t2h, pW1, b1, nullptr, p_ffh, BB * GG, FF, DD, 1.f);
    tc_gemm<0, 0><<<dim3(DD / 128, (BB * GG) / 128), 256, GEMM_SMEM>>>(
        p_ffh, pW2, b2, p_ffn2, nullptr, BB * GG, DD, FF, 1.f);
    ln_kernel<<<BB * GG, 256>>>(p_ffn2, p_t2, g3, beta3, p_oproj, nullptr, 2);

    // GroupFC
    groupfc_kernel<<<dim3(BB / 64, GG), 256>>>(p_oproj, Wg, bg, out);
}

// round 10
// speedup vs baseline: 4.4591x; 1.0599x over previous
#include <cuda_runtime.h>
#include <cuda_fp16.h>
#include <math.h>
#include <stdint.h>

// ---------------- problem constants ----------------
#define BB 128      // batch
#define NN 49       // spatial tokens
#define CIN 2048
#define GG 256      // query groups
#define DD 768      // model dim
#define HH 8        // heads
#define HD 96       // head dim
#define FF 2048
#define NCLS 12547
#define DUP 50

// ---------------- asm helpers (sm_80+ features only) -------------------------
__device__ __forceinline__ uint32_t smem_u32(const void* p) {
    uint32_t a;
    asm("{ .reg .u64 t; cvta.to.shared.u64 t, %1; cvt.u32.u64 %0, t; }" : "=r"(a) : "l"(p));
    return a;
}
#define CP16(dst, src) \
    asm volatile("cp.async.cg.shared.global [%0], [%1], 16;" :: "r"(dst), "l"(src))
#define CP_COMMIT() asm volatile("cp.async.commit_group;" ::: "memory")
#define CP_WAIT(n)  asm volatile("cp.async.wait_group %0;" :: "n"(n) : "memory")
#define LDSM4(r, addr) \
    asm volatile("ldmatrix.sync.aligned.m8n8.x4.shared.b16 {%0,%1,%2,%3}, [%4];" \
                 : "=r"((r)[0]), "=r"((r)[1]), "=r"((r)[2]), "=r"((r)[3]) : "r"(addr))
#define MMA_F16(c, a, b0, b1) \
    asm volatile("mma.sync.aligned.m16n8k16.row.col.f32.f16.f16.f32 " \
                 "{%0,%1,%2,%3},{%4,%5,%6,%7},{%8,%9},{%0,%1,%2,%3};" \
                 : "+f"((c)[0]), "+f"((c)[1]), "+f"((c)[2]), "+f"((c)[3]) \
                 : "r"((a)[0]), "r"((a)[1]), "r"((a)[2]), "r"((a)[3]), "r"(b0), "r"(b1))

// ---------------- scratch (device globals) -----------------------------------
// fp32
__device__ float g_k    [BB * NN * DD];
__device__ float g_v    [BB * NN * DD];
__device__ float g_t1   [GG * DD];
__device__ float g_q    [GG * DD];
__device__ float g_oproj[BB * GG * DD];   // Wo out; later reused as h
__device__ float g_t2   [BB * GG * DD];
__device__ float g_ffn2 [BB * GG * DD];
// fp16 activation operands
__device__ __half g_xh [BB * NN * CIN];
__device__ __half g_mh [BB * NN * DD];
__device__ __half g_t1h[GG * DD];
__device__ __half g_aoh[BB * GG * DD];
__device__ __half g_t2h[BB * GG * DD];
__device__ __half g_ffh[BB * GG * FF];
// transposed fp16 weights: [N,K]
__device__ __half tWe[DD * CIN];
__device__ __half tWq[DD * DD];
__device__ __half tWk[DD * DD];
__device__ __half tWv[DD * DD];
__device__ __half tWo[DD * DD];
__device__ __half tW1[FF * DD];
__device__ __half tW2[DD * FF];

// ---------------- weight transpose: W[K,N] fp32 -> [N,K] fp16 ----------------
__global__ __launch_bounds__(256)
void transpose_half(const float* __restrict__ W, __half* __restrict__ o,
                    int K, int N)
{
    __shared__ float tile[32][33];
    const int tx = threadIdx.x & 31, ty = threadIdx.x >> 5;
    const int kb = blockIdx.y * 32, nb = blockIdx.x * 32;
    #pragma unroll
    for (int i = 0; i < 4; i++)
        tile[ty + i * 8][tx] = W[(size_t)(kb + ty + i * 8) * N + nb + tx];
    __syncthreads();
    #pragma unroll
    for (int i = 0; i < 4; i++) {
        const int n = nb + ty + i * 8, k = kb + tx;
        o[(size_t)n * K + k] = __float2half(tile[tx][ty + i * 8]);
    }
}

// ---------------- elementwise fp32 -> fp16 (for x) ---------------------------
__global__ __launch_bounds__(256)
void convert_half(const float* __restrict__ in, __half* __restrict__ out)
{
    const int i = (blockIdx.x * 256 + threadIdx.x) * 4;
    float4 v = *reinterpret_cast<const float4*>(in + i);
    __half2 a(__float2half(v.x), __float2half(v.y));
    __half2 b(__float2half(v.z), __float2half(v.w));
    *reinterpret_cast<__half2*>(out + i)     = a;
    *reinterpret_cast<__half2*>(out + i + 2) = b;
}

// ---------------- fp16 single-pass tensor-core GEMM --------------------------
// C = act(alpha*(A @ B^T + bias));  A [M,K] fp16, B [N,K] fp16.
// BM=BN=128, BK=32; 4 warps x (64x64) warp tiles; 3-stage cp.async pipeline.
// M%128==0, N%128==0, K%32==0.
#define LDSH 40                      // smem row stride in halves (80B, conflict-free)
#define TILE_B (128 * LDSH * 2)      // 10240B per tile
#define STAGE_B (2 * TILE_B)         // 20480B per stage (A, B)
#define NSTAGE 3
#define GEMM_SMEM (NSTAGE * STAGE_B) // 61440B

template <int RELU, int HOUT>
__global__ __launch_bounds__(128, 2)
void tc_gemm(const __half* __restrict__ A, const __half* __restrict__ B,
             const float* __restrict__ bias,
             float* __restrict__ Cf, __half* __restrict__ Ch,
             int M, int N, int K, float alpha)
{
    extern __shared__ __half sm[];
    const uint32_t sb = smem_u32(sm);
    const int tid = threadIdx.x, wid = tid >> 5, lane = tid & 31;
    const int wm = wid & 1, wn = wid >> 1;             // warp tile: rows wm*64, cols wn*64
    const int m0 = blockIdx.y * 128, n0 = blockIdx.x * 128;
    const int nst = K >> 5;

    // ---- async stage loader: 8 x 16B per thread (A 4, B 4) ----
    auto load_stage = [&](int s, int buf) {
        const int k0 = s << 5;
        const uint32_t d0 = sb + buf * STAGE_B;
        #pragma unroll
        for (int i = 0; i < 8; i++) {
            const int isA = (i < 4);
            const int c = (i & 3) * 128 + tid;           // 0..511 chunk within tile
            const int row = c >> 2, part = c & 3;
            const __half* src = (isA ? A + (size_t)(m0 + row) * K
                                     : B + (size_t)(n0 + row) * K) + k0 + part * 8;
            const uint32_t dst = d0 + (isA ? 0 : TILE_B) + row * (LDSH * 2) + part * 16;
            CP16(dst, src);
        }
        CP_COMMIT();
    };

    float acc[4][8][4];
    #pragma unroll
    for (int i = 0; i < 4; i++)
        #pragma unroll
        for (int j = 0; j < 8; j++)
            #pragma unroll
            for (int q = 0; q < 4; q++) acc[i][j][q] = 0.f;

    load_stage(0, 0);
    if (1 < nst) load_stage(1, 1); else CP_COMMIT();

    // ldmatrix lane addressing (halves)
    const int a_r = (lane & 15), a_c8 = (lane >> 4) * 8;
    const int b_r = ((lane >> 4) & 1) * 8 + (lane & 7);
    const int b_c8 = ((lane >> 3) & 1) * 8;

    int buf = 0;
    #pragma unroll 1
    for (int s = 0; s < nst; s++) {
        // prefetch s+2 into the buffer freed at end of iteration s-1
        // FIX (R9 crash): modular wrap for buf==2 -> pb must be 1, not 4.
        const int pb = (buf + 2 >= NSTAGE) ? (buf + 2 - NSTAGE) : (buf + 2);
        if (s + 2 < nst) load_stage(s + 2, pb); else CP_COMMIT();
        CP_WAIT(2);                     // uniform commits -> stage s resident
        __syncthreads();

        const uint32_t ab = sb + buf * STAGE_B;
        const uint32_t bb = ab + TILE_B;

        #pragma unroll
        for (int ks = 0; ks < 2; ks++) {
            const int kh = ks * 16;
            uint32_t fA[4][4], fB[4][4];
            #pragma unroll
            for (int i = 0; i < 4; i++) {
                const uint32_t off = ((wm * 64 + i * 16 + a_r) * LDSH + kh + a_c8) * 2;
                LDSM4(fA[i], ab + off);
            }
            #pragma unroll
            for (int j = 0; j < 4; j++) {
                const uint32_t off = ((wn * 64 + j * 16 + b_r) * LDSH + kh + b_c8) * 2;
                LDSM4(fB[j], bb + off);
            }
            #pragma unroll
            for (int n = 0; n < 8; n++) {
                const int j = n >> 1, h = (n & 1) * 2;
                const uint32_t b0 = fB[j][h], b1 = fB[j][h + 1];
                #pragma unroll
                for (int i = 0; i < 4; i++)
                    MMA_F16(acc[i][n], fA[i], b0, b1);
            }
        }
        __syncthreads();
        buf = (buf + 1 == NSTAGE) ? 0 : (buf + 1);
    }

    // ---- epilogue ----
    const int row0 = m0 + wm * 64 + (lane >> 2);
    const int col0 = n0 + wn * 64 + (lane & 3) * 2;
    #pragma unroll
    for (int i = 0; i < 4; i++) {
        #pragma unroll
        for (int j = 0; j < 8; j++) {
            const int r = row0 + i * 16;
            const int c = col0 + j * 8;
            const float b0 = bias[c], b1 = bias[c + 1];
            float v0 = alpha * (acc[i][j][0] + b0);
            float v1 = alpha * (acc[i][j][1] + b1);
            float v2 = alpha * (acc[i][j][2] + b0);
            float v3 = alpha * (acc[i][j][3] + b1);
            if (RELU) {
                v0 = fmaxf(v0, 0.f); v1 = fmaxf(v1, 0.f);
                v2 = fmaxf(v2, 0.f); v3 = fmaxf(v3, 0.f);
            }
            if (!HOUT) {
                *reinterpret_cast<float2*>(Cf + (size_t)r * N + c)       = make_float2(v0, v1);
                *reinterpret_cast<float2*>(Cf + (size_t)(r + 8) * N + c) = make_float2(v2, v3);
            } else {
                *reinterpret_cast<__half2*>(Ch + (size_t)r * N + c) =
                    __half2(__float2half(v0), __float2half(v1));
                *reinterpret_cast<__half2*>(Ch + (size_t)(r + 8) * N + c) =
                    __half2(__float2half(v2), __float2half(v3));
            }
        }
    }
}

// ---------------- LayerNorm over D=768 (optional fp16 side output) -----------
__global__ __launch_bounds__(256)
void ln_kernel(const float* __restrict__ a, const float* __restrict__ r,
               const float* __restrict__ gamma, const float* __restrict__ beta,
               float* __restrict__ out, __half* __restrict__ oh, int mode)
{
    const int row = blockIdx.x;
    const int t = threadIdx.x;
    const float* ap = a + (size_t)row * DD;

    float x[3];
    #pragma unroll
    for (int j = 0; j < 3; j++) {
        const int idx = t + j * 256;
        float val = ap[idx];
        if (mode == 0)      val = 2.f * val;
        else if (mode == 1) val += r[(size_t)(row & (GG - 1)) * DD + idx];
        else                val += r[(size_t)row * DD + idx];
        x[j] = val;
    }
    float s1 = x[0] + x[1] + x[2];
    float s2 = x[0] * x[0] + x[1] * x[1] + x[2] * x[2];
    #pragma unroll
    for (int off = 16; off; off >>= 1) {
        s1 += __shfl_xor_sync(0xffffffffu, s1, off);
        s2 += __shfl_xor_sync(0xffffffffu, s2, off);
    }
    __shared__ float sh1[8], sh2[8];
    const int w = t >> 5, lane = t & 31;
    if (lane == 0) { sh1[w] = s1; sh2[w] = s2; }
    __syncthreads();
    float S1 = 0.f, S2 = 0.f;
    #pragma unroll
    for (int i = 0; i < 8; i++) { S1 += sh1[i]; S2 += sh2[i]; }
    const float mean = S1 * (1.f / (float)DD);
    const float var  = S2 * (1.f / (float)DD) - mean * mean;
    const float rstd = rsqrtf(var + 1e-5f);

    #pragma unroll
    for (int j = 0; j < 3; j++) {
        const int idx = t + j * 256;
        const float v = (x[j] - mean) * rstd * gamma[idx] + beta[idx];
        out[(size_t)row * DD + idx] = v;
        if (oh) oh[(size_t)row * DD + idx] = __float2half(v);
    }
}

// ---------------- fused cross-attention, fp16 output -------------------------
__global__ __launch_bounds__(256)
void attn_kernel(const float* __restrict__ q, const float* __restrict__ k,
                 const float* __restrict__ v, __half* __restrict__ oh)
{
    __shared__ float ks[NN][HD];
    __shared__ float vs[NN][HD];
    const int h = blockIdx.x, b = blockIdx.y;
    const int t = threadIdx.x;

    for (int i = t; i < NN * HD; i += 256) {
        const int n = i / HD, d = i % HD;
        const size_t gi = ((size_t)(b * NN + n)) * DD + h * HD + d;
        ks[n][d] = k[gi];
        vs[n][d] = v[gi];
    }
    __syncthreads();

    const int g = t;
    float4 qv[HD / 4];
    const float4* qp = reinterpret_cast<const float4*>(q + (size_t)g * DD + h * HD);
    #pragma unroll
    for (int i = 0; i < HD / 4; i++) qv[i] = qp[i];

    float s[NN];
    #pragma unroll 7
    for (int n = 0; n < NN; n++) {
        const float4* kp = reinterpret_cast<const float4*>(ks[n]);
        float acc = 0.f;
        #pragma unroll
        for (int i = 0; i < HD / 4; i++) {
            float4 kk = kp[i];
            acc += qv[i].x * kk.x + qv[i].y * kk.y + qv[i].z * kk.z + qv[i].w * kk.w;
        }
        s[n] = acc;
    }
    float m = -1e30f;
    #pragma unroll
    for (int n = 0; n < NN; n++) m = fmaxf(m, s[n]);
    float sum = 0.f;
    #pragma unroll
    for (int n = 0; n < NN; n++) { s[n] = __expf(s[n] - m); sum += s[n]; }
    const float inv = 1.f / sum;

    const size_t ob = ((size_t)(b * GG + g)) * DD + h * HD;
    #pragma unroll
    for (int d4 = 0; d4 < HD / 4; d4++) {
        float4 acc = {0.f, 0.f, 0.f, 0.f};
        #pragma unroll 7
        for (int n = 0; n < NN; n++) {
            const float p = s[n];
            float4 vv = *reinterpret_cast<const float4*>(&vs[n][d4 * 4]);
            acc.x += p * vv.x; acc.y += p * vv.y; acc.z += p * vv.z; acc.w += p * vv.w;
        }
        acc.x *= inv; acc.y *= inv; acc.z *= inv; acc.w *= inv;
        *reinterpret_cast<__half2*>(oh + ob + d4 * 4) =
            __half2(__float2half(acc.x), __float2half(acc.y));
        *reinterpret_cast<__half2*>(oh + ob + d4 * 4 + 2) =
            __half2(__float2half(acc.z), __float2half(acc.w));
    }
}

// ---------------- GroupFC ----------------------------------------------------
__global__ __launch_bounds__(256)
void groupfc_kernel(const float* __restrict__ h, const float* __restrict__ Wg,
                    const float* __restrict__ bg, float* __restrict__ out)
{
    const int g  = blockIdx.y;
    const int b0 = blockIdx.x * 64;
    __shared__ float hs[32][65];
    __shared__ float ws[32][65];
    const int t = threadIdx.x;
    const int tx = (t % 16) * 4;
    const int ty = (t / 16) * 4;
    float acc[4][4] = {};

    for (int d0 = 0; d0 < DD; d0 += 32) {
        for (int i = t; i < 64 * 32; i += 256) {
            const int bi = i / 32, di = i % 32;
            hs[di][bi] = h[((size_t)(b0 + bi) * GG + g) * DD + d0 + di];
        }
        for (int i = t; i < 32 * 64; i += 256) {
            const int di = i / 64, fi = i % 64;
            ws[di][fi] = (fi < DUP) ? Wg[((size_t)g * DD + d0 + di) * DUP + fi] : 0.f;
        }
        __syncthreads();
        #pragma unroll
        for (int d = 0; d < 32; d++) {
            float rh[4], rb[4];
            #pragma unroll
            for (int i = 0; i < 4; i++) rh[i] = hs[d][ty + i];
            #pragma unroll
            for (int j = 0; j < 4; j++) rb[j] = ws[d][tx + j];
            #pragma unroll
            for (int i = 0; i < 4; i++)
                #pragma unroll
                for (int j = 0; j < 4; j++)
                    acc[i][j] += rh[i] * rb[j];
        }
        __syncthreads();
    }
    #pragma unroll
    for (int i = 0; i < 4; i++) {
        #pragma unroll
        for (int j = 0; j < 4; j++) {
            const int f = tx + j;
            if (f < DUP) {
                const int c = g * DUP + f;
                if (c < NCLS)
                    out[(size_t)(b0 + ty + i) * NCLS + c] = acc[i][j] + bg[c];
            }
        }
    }
}

// ---------------- launch -----------------------------------------------------
static float* sym(const void* s) { void* p = nullptr; cudaGetSymbolAddress(&p, s); return (float*)p; }
static __half* symh(const void* s) { void* p = nullptr; cudaGetSymbolAddress(&p, s); return (__half*)p; }

extern "C" void kernel_launch(void* const* d_in, const int* in_sizes, int n_in,
                              void* d_out, int out_size)
{
    (void)in_sizes; (void)n_in; (void)out_size;
    const float* x      = (const float*)d_in[0];
    const float* We     = (const float*)d_in[1];
    const float* be     = (const float*)d_in[2];
    const float* query  = (const float*)d_in[3];
    const float* Wq     = (const float*)d_in[4];
    const float* bq     = (const float*)d_in[5];
    const float* Wk     = (const float*)d_in[6];
    const float* bk     = (const float*)d_in[7];
    const float* Wv     = (const float*)d_in[8];
    const float* bv     = (const float*)d_in[9];
    const float* Wo     = (const float*)d_in[10];
    const float* bo     = (const float*)d_in[11];
    const float* g1     = (const float*)d_in[12];
    const float* beta1  = (const float*)d_in[13];
    const float* g2     = (const float*)d_in[14];
    const float* beta2  = (const float*)d_in[15];
    const float* g3     = (const float*)d_in[16];
    const float* beta3  = (const float*)d_in[17];
    const float* W1     = (const float*)d_in[18];
    const float* b1     = (const float*)d_in[19];
    const float* W2     = (const float*)d_in[20];
    const float* b2     = (const float*)d_in[21];
    const float* Wg     = (const float*)d_in[22];
    const float* bg     = (const float*)d_in[23];
    float* out = (float*)d_out;

    float *p_k = sym(g_k), *p_v = sym(g_v), *p_t1 = sym(g_t1), *p_q = sym(g_q);
    float *p_oproj = sym(g_oproj), *p_t2 = sym(g_t2), *p_ffn2 = sym(g_ffn2);
    __half *p_xh = symh(g_xh), *p_mh = symh(g_mh), *p_t1h = symh(g_t1h);
    __half *p_aoh = symh(g_aoh), *p_t2h = symh(g_t2h), *p_ffh = symh(g_ffh);
    __half *pWe = symh(tWe), *pWq = symh(tWq), *pWk = symh(tWk), *pWv = symh(tWv);
    __half *pWo = symh(tWo), *pW1 = symh(tW1), *pW2 = symh(tW2);

    cudaFuncSetAttribute(tc_gemm<0, 0>, cudaFuncAttributeMaxDynamicSharedMemorySize, GEMM_SMEM);
    cudaFuncSetAttribute(tc_gemm<0, 1>, cudaFuncAttributeMaxDynamicSharedMemorySize, GEMM_SMEM);
    cudaFuncSetAttribute(tc_gemm<1, 1>, cudaFuncAttributeMaxDynamicSharedMemorySize, GEMM_SMEM);

    const float qscale = 0.10206207261596577f;  // 1/sqrt(96)

    // weight transpose -> fp16 [N,K]
    transpose_half<<<dim3(DD / 32, CIN / 32), 256>>>(We, pWe, CIN, DD);
    transpose_half<<<dim3(DD / 32, DD / 32), 256>>>(Wq, pWq, DD, DD);
    transpose_half<<<dim3(DD / 32, DD / 32), 256>>>(Wk, pWk, DD, DD);
    transpose_half<<<dim3(DD / 32, DD / 32), 256>>>(Wv, pWv, DD, DD);
    transpose_half<<<dim3(DD / 32, DD / 32), 256>>>(Wo, pWo, DD, DD);
    transpose_half<<<dim3(FF / 32, DD / 32), 256>>>(W1, pW1, DD, FF);
    transpose_half<<<dim3(DD / 32, FF / 32), 256>>>(W2, pW2, FF, DD);
    // x -> fp16
    convert_half<<<(BB * NN * CIN) / 1024, 256>>>(x, p_xh);

    // t1 = LN(2*query) (+fp16); q = (t1@Wq + bq)/sqrt(96)
    ln_kernel<<<GG, 256>>>(query, nullptr, g1, beta1, p_t1, p_t1h, 0);
    tc_gemm<0, 0><<<dim3(DD / 128, GG / 128), 128, GEMM_SMEM>>>(
        p_t1h, pWq, bq, p_q, nullptr, GG, DD, DD, qscale);

    // mem = relu(x @ We + be)  -> fp16 directly
    tc_gemm<1, 1><<<dim3(DD / 128, (BB * NN) / 128), 128, GEMM_SMEM>>>(
        p_xh, pWe, be, nullptr, p_mh, BB * NN, DD, CIN, 1.f);
    // k, v projections (fp32 out for attention)
    tc_gemm<0, 0><<<dim3(DD / 128, (BB * NN) / 128), 128, GEMM_SMEM>>>(
        p_mh, pWk, bk, p_k, nullptr, BB * NN, DD, DD, 1.f);
    tc_gemm<0, 0><<<dim3(DD / 128, (BB * NN) / 128), 128, GEMM_SMEM>>>(
        p_mh, pWv, bv, p_v, nullptr, BB * NN, DD, DD, 1.f);

    // fused attention -> fp16
    attn_kernel<<<dim3(HH, BB), 256>>>(p_q, p_k, p_v, p_aoh);

    // output projection + residual LN (t2 fp32 + fp16)
    tc_gemm<0, 0><<<dim3(DD / 128, (BB * GG) / 128), 128, GEMM_SMEM>>>(
        p_aoh, pWo, bo, p_oproj, nullptr, BB * GG, DD, DD, 1.f);
    ln_kernel<<<BB * GG, 256>>>(p_oproj, p_t1, g2, beta2, p_t2, p_t2h, 1);

    // FFN: ff = relu(t2@W1+b1) -> fp16; ffn2 = ff@W2+b2 -> fp32
    tc_gemm<1, 1><<<dim3(FF / 128, (BB * GG) / 128), 128, GEMM_SMEM>>>(
        p_t2h, pW1, b1, nullptr, p_ffh, BB * GG, FF, DD, 1.f);
    tc_gemm<0, 0><<<dim3(DD / 128, (BB * GG) / 128), 128, GEMM_SMEM>>>(
        p_ffh, pW2, b2, p_ffn2, nullptr, BB * GG, DD, FF, 1.f);
    ln_kernel<<<BB * GG, 256>>>(p_ffn2, p_t2, g3, beta3, p_oproj, nullptr, 2);

    // GroupFC
    groupfc_kernel<<<dim3(BB / 64, GG), 256>>>(p_oproj, Wg, bg, out);
}